// round 1
// baseline (speedup 1.0000x reference)
#include <cuda_runtime.h>

#define NN 163840
#define NE 2621440
#define NB 4096
#define NPG 40          // nodes per graph

// ---------------- device scratch (static, no allocations) ----------------
__device__ float g_u[NN * 312];      // X @ W, row-scaled by dinv  (padded stride)
__device__ float g_S[NN * 312];      // scatter accumulator
__device__ float g_h[NN * 312];      // layer output (ping buffer, reused)
__device__ float g_dinv[NN];
__device__ int   g_deg[NN];
__device__ float g_g[NB * 312];      // graph max-pool
__device__ float g_gh[NB * 1024];
__device__ float g_c[NB * 256];      // concat [g2 | t]
__device__ float g_c1[NB * 1024];
__device__ float g_c2[NB * 128];
__device__ float g_tf[NB * 2944];    // flattened conv features
__device__ float g_k2t[32 * 8 * 64];   // k2 transposed to [ic][tap][oc]
__device__ float g_k3t[64 * 8 * 128];  // k3 transposed to [ic][tap][oc]

// ---------------- small utility kernels ----------------
__global__ void k_zero_f4(float4* p, int n4) {
    int i = blockIdx.x * blockDim.x + threadIdx.x;
    if (i < n4) p[i] = make_float4(0.f, 0.f, 0.f, 0.f);
}
__global__ void k_zero_i(int* p, int n) {
    int i = blockIdx.x * blockDim.x + threadIdx.x;
    if (i < n) p[i] = 0;
}
__global__ void k_degree(const int* __restrict__ dst, int* __restrict__ deg) {
    int e = blockIdx.x * blockDim.x + threadIdx.x;
    if (e < NE) atomicAdd(&deg[dst[e]], 1);
}
__global__ void k_dinv(const int* __restrict__ deg, float* __restrict__ dinv) {
    int i = blockIdx.x * blockDim.x + threadIdx.x;
    if (i < NN) dinv[i] = rsqrtf((float)deg[i] + 1.0f);
}

// ---------------- generic fp32 GEMM: C = act((A@W)*rowScale + bias) ----------------
// A: [M,K] lda ; W: [K,Ncol] dense ; C: [M, ...] ldc, cols [0,Npad) written, cols>=Ncol get 0.
__global__ void k_gemm(const float* __restrict__ A, int lda,
                       const float* __restrict__ W,
                       const float* __restrict__ bias,
                       const float* __restrict__ rowScale,
                       float* __restrict__ C, int ldc,
                       int M, int K, int Ncol, int Npad, int doRelu)
{
    __shared__ float As[16][65];
    __shared__ float Ws[16][65];
    int tid = threadIdx.x;          // 256 threads
    int tx = tid & 15, ty = tid >> 4;
    int rowBase = blockIdx.y * 64;
    int colBase = blockIdx.x * 64;
    float acc[4][4];
#pragma unroll
    for (int i = 0; i < 4; i++)
#pragma unroll
        for (int j = 0; j < 4; j++) acc[i][j] = 0.f;

    for (int k0 = 0; k0 < K; k0 += 16) {
#pragma unroll
        for (int l = 0; l < 4; l++) {
            int idx = tid + l * 256;
            int mm = idx >> 4, kk = idx & 15;
            int m = rowBase + mm, k = k0 + kk;
            float v = 0.f;
            if (m < M && k < K) v = A[(long)m * lda + k];
            As[kk][mm] = v;
        }
#pragma unroll
        for (int l = 0; l < 4; l++) {
            int idx = tid + l * 256;
            int kk = idx >> 6, nn = idx & 63;
            int k = k0 + kk, n = colBase + nn;
            float v = 0.f;
            if (k < K && n < Ncol) v = W[(long)k * Ncol + n];
            Ws[kk][nn] = v;
        }
        __syncthreads();
#pragma unroll
        for (int kk = 0; kk < 16; kk++) {
            float a[4], b[4];
#pragma unroll
            for (int i = 0; i < 4; i++) a[i] = As[kk][ty * 4 + i];
#pragma unroll
            for (int j = 0; j < 4; j++) b[j] = Ws[kk][tx * 4 + j];
#pragma unroll
            for (int i = 0; i < 4; i++)
#pragma unroll
                for (int j = 0; j < 4; j++) acc[i][j] = fmaf(a[i], b[j], acc[i][j]);
        }
        __syncthreads();
    }
#pragma unroll
    for (int i = 0; i < 4; i++) {
        int m = rowBase + ty * 4 + i;
        if (m >= M) continue;
        float rs = rowScale ? rowScale[m] : 1.f;
#pragma unroll
        for (int j = 0; j < 4; j++) {
            int n = colBase + tx * 4 + j;
            if (n >= Npad) continue;
            float v = 0.f;
            if (n < Ncol) {
                v = acc[i][j] * rs;
                if (bias) v += bias[n];
                if (doRelu) v = fmaxf(v, 0.f);
            }
            C[(long)m * ldc + n] = v;
        }
    }
}

// ---------------- edge scatter: S[dst] += u[src]  (v4 reductions) ----------------
template <int CH>   // CH = padded_feature_dim / 4
__global__ void k_scatter(const float* __restrict__ u, float* __restrict__ S,
                          const int* __restrict__ src, const int* __restrict__ dst)
{
    long idx = (long)blockIdx.x * blockDim.x + threadIdx.x;
    if (idx >= (long)NE * CH) return;
    int e = (int)(idx / CH);
    int c = (int)(idx - (long)e * CH);
    int s = src[e], d = dst[e];
    const int stride = CH * 4;
    float4 v = *(const float4*)(u + (long)s * stride + c * 4);
    float* p = S + (long)d * stride + c * 4;
    asm volatile("red.global.add.v4.f32 [%0], {%1, %2, %3, %4};"
                 :: "l"(p), "f"(v.x), "f"(v.y), "f"(v.z), "f"(v.w) : "memory");
}

// h = relu(dinv*(S + u) + b)
__global__ void k_combine(const float* __restrict__ u, const float* __restrict__ S,
                          const float* __restrict__ dinv, const float* __restrict__ bias,
                          float* __restrict__ h, int F, int Fpad)
{
    int idx = blockIdx.x * blockDim.x + threadIdx.x;
    if (idx >= NN * F) return;
    int i = idx / F, f = idx - i * F;
    int off = i * Fpad + f;
    h[off] = fmaxf(dinv[i] * (S[off] + u[off]) + bias[f], 0.f);
}

// per-graph max pool over 40 contiguous nodes, F=312 stride 312
__global__ void k_segmax(const float* __restrict__ h, float* __restrict__ g)
{
    int b = blockIdx.x;
    const float* p = h + (long)b * NPG * 312;
    for (int f = threadIdx.x; f < 312; f += blockDim.x) {
        float m = -3.4e38f;
#pragma unroll 4
        for (int n = 0; n < NPG; n++) m = fmaxf(m, p[n * 312 + f]);
        g[b * 312 + f] = m;
    }
}

// ---------------- conv weight transposes ----------------
__global__ void k_tr_k2(const float* __restrict__ k2, float* __restrict__ k2t) {
    int idx = blockIdx.x * blockDim.x + threadIdx.x;
    if (idx >= 64 * 32 * 8) return;
    int oc = idx >> 8, r = idx & 255, ic = r >> 3, i = r & 7;
    k2t[(ic * 8 + i) * 64 + oc] = k2[idx];
}
__global__ void k_tr_k3(const float* __restrict__ k3, float* __restrict__ k3t) {
    int idx = blockIdx.x * blockDim.x + threadIdx.x;
    if (idx >= 128 * 64 * 8) return;
    int oc = idx >> 9, r = idx & 511, ic = r >> 3, i = r & 7;
    k3t[(ic * 8 + i) * 128 + oc] = k3[idx];
}

// ---------------- fused conv tower: one CTA per graph ----------------
// smem floats: t1[32*242]=7744 at 0 ; region2 at 7744: stage1 {in 735, k1 256, kb1 32},
// stage2+ t2[64*78]=4992 ; t3[128*23]=2944 at 0 (after stage2). Total 12736 floats.
__global__ void k_conv(const float* __restrict__ xo,
                       const float* __restrict__ k1, const float* __restrict__ kb1,
                       const float* __restrict__ k2t, const float* __restrict__ kb2,
                       const float* __restrict__ k3t, const float* __restrict__ kb3,
                       float* __restrict__ tf)
{
    extern __shared__ float sm[];
    const int S_T1 = 0, S_T2 = 7744, S_IN = 7744, S_K1 = 8480, S_KB1 = 8736, S_T3 = 0;
    int b = blockIdx.x;
    int tid = threadIdx.x;

    for (int i = tid; i < 735; i += 256) sm[S_IN + i] = xo[(long)b * 735 + i];
    if (tid < 256) sm[S_K1 + tid] = k1[tid];
    if (tid < 32)  sm[S_KB1 + tid] = kb1[tid];
    __syncthreads();

    // stage 1: conv(1->32,k8) + relu + pool3 -> t1[32][242]
    for (int o = tid; o < 32 * 242; o += 256) {
        int ch = o / 242;
        int p = o - ch * 242;
        int base = 3 * p;
        const float* w = &sm[S_K1 + ch * 8];
        float s0 = 0.f, s1 = 0.f, s2 = 0.f;
#pragma unroll
        for (int i = 0; i < 8; i++) {
            float wv = w[i];
            s0 = fmaf(sm[S_IN + base + i],     wv, s0);
            s1 = fmaf(sm[S_IN + base + 1 + i], wv, s1);
            s2 = fmaf(sm[S_IN + base + 2 + i], wv, s2);
        }
        float m = fmaxf(fmaxf(s0, s1), s2) + sm[S_KB1 + ch];
        sm[S_T1 + o] = fmaxf(m, 0.f);
    }
    __syncthreads();

    // stage 2: conv(32->64,k8) + relu + pool3 -> t2[64][78]
    {
        int oc = tid & 63;
        int pt = tid >> 6;                 // 4 tiles of 20 pooled positions
        float bb = kb2[oc];
        for (int c4 = 0; c4 < 5; c4++) {
            int p0 = pt * 20 + c4 * 4;
            int q0 = 3 * p0;
            float acc[12];
#pragma unroll
            for (int r = 0; r < 12; r++) acc[r] = 0.f;
            for (int ic = 0; ic < 32; ic++) {
                float w[8];
#pragma unroll
                for (int i = 0; i < 8; i++) w[i] = k2t[(ic * 8 + i) * 64 + oc];
                const float* t1r = &sm[S_T1 + ic * 242];
                float inb[19];
#pragma unroll
                for (int i = 0; i < 19; i++) {
                    int q = q0 + i;
                    inb[i] = t1r[q < 242 ? q : 241];
                }
#pragma unroll
                for (int r = 0; r < 12; r++)
#pragma unroll
                    for (int i = 0; i < 8; i++)
                        acc[r] = fmaf(inb[r + i], w[i], acc[r]);
            }
#pragma unroll
            for (int pp = 0; pp < 4; pp++) {
                int p = p0 + pp;
                if (p < 78) {
                    float m = fmaxf(fmaxf(acc[3 * pp], acc[3 * pp + 1]), acc[3 * pp + 2]) + bb;
                    sm[S_T2 + oc * 78 + p] = fmaxf(m, 0.f);
                }
            }
        }
    }
    __syncthreads();

    // stage 3: conv(64->128,k8) + relu + pool3 -> t3[128][23] (at offset 0)
    {
        int oc = tid & 127;
        int pt = tid >> 7;                 // 2 tiles of 12 pooled positions
        float bb = kb3[oc];
        for (int c4 = 0; c4 < 3; c4++) {
            int p0 = pt * 12 + c4 * 4;
            int q0 = 3 * p0;
            float acc[12];
#pragma unroll
            for (int r = 0; r < 12; r++) acc[r] = 0.f;
            for (int ic = 0; ic < 64; ic++) {
                float w[8];
#pragma unroll
                for (int i = 0; i < 8; i++) w[i] = k3t[(ic * 8 + i) * 128 + oc];
                const float* t2r = &sm[S_T2 + ic * 78];
                float inb[19];
#pragma unroll
                for (int i = 0; i < 19; i++) {
                    int q = q0 + i;
                    inb[i] = t2r[q < 78 ? q : 77];
                }
#pragma unroll
                for (int r = 0; r < 12; r++)
#pragma unroll
                    for (int i = 0; i < 8; i++)
                        acc[r] = fmaf(inb[r + i], w[i], acc[r]);
            }
#pragma unroll
            for (int pp = 0; pp < 4; pp++) {
                int p = p0 + pp;
                if (p < 23) {
                    float m = fmaxf(fmaxf(acc[3 * pp], acc[3 * pp + 1]), acc[3 * pp + 2]) + bb;
                    sm[S_T3 + oc * 23 + p] = fmaxf(m, 0.f);
                }
            }
        }
    }
    __syncthreads();

    for (int i = tid; i < 2944; i += 256) tf[(long)b * 2944 + i] = sm[S_T3 + i];
}

// final dot: out[b] = c2[b,:] . Wo + bo
__global__ void k_out(const float* __restrict__ c2, const float* __restrict__ Wo,
                      const float* __restrict__ bo, float* __restrict__ out)
{
    int warp = (blockIdx.x * blockDim.x + threadIdx.x) >> 5;
    int lane = threadIdx.x & 31;
    if (warp >= NB) return;
    float s = 0.f;
#pragma unroll
    for (int i = lane; i < 128; i += 32) s = fmaf(c2[warp * 128 + i], Wo[i], s);
#pragma unroll
    for (int off = 16; off; off >>= 1) s += __shfl_down_sync(0xffffffffu, s, off);
    if (lane == 0) out[warp] = s + bo[0];
}

// ---------------- launch ----------------
static inline int cdiv(long a, long b) { return (int)((a + b - 1) / b); }

extern "C" void kernel_launch(void* const* d_in, const int* in_sizes, int n_in,
                              void* d_out, int out_size)
{
    const float* x    = (const float*)d_in[0];
    const int*   ei   = (const int*)d_in[1];
    const float* xo   = (const float*)d_in[3];
    const float* W1   = (const float*)d_in[4];  const float* b1  = (const float*)d_in[5];
    const float* W2   = (const float*)d_in[6];  const float* b2  = (const float*)d_in[7];
    const float* W3   = (const float*)d_in[8];  const float* b3  = (const float*)d_in[9];
    const float* Wg1  = (const float*)d_in[10]; const float* bg1 = (const float*)d_in[11];
    const float* Wg2  = (const float*)d_in[12]; const float* bg2 = (const float*)d_in[13];
    const float* k1   = (const float*)d_in[14]; const float* kb1 = (const float*)d_in[15];
    const float* k2   = (const float*)d_in[16]; const float* kb2 = (const float*)d_in[17];
    const float* k3   = (const float*)d_in[18]; const float* kb3 = (const float*)d_in[19];
    const float* Wxt  = (const float*)d_in[20]; const float* bxt = (const float*)d_in[21];
    const float* Wf1  = (const float*)d_in[22]; const float* bf1 = (const float*)d_in[23];
    const float* Wf2  = (const float*)d_in[24]; const float* bf2 = (const float*)d_in[25];
    const float* Wo   = (const float*)d_in[26]; const float* bo  = (const float*)d_in[27];
    const int* src = ei;
    const int* dst = ei + NE;
    float* out = (float*)d_out;

    float *p_u, *p_S, *p_h, *p_dinv, *p_g, *p_gh, *p_c, *p_c1, *p_c2, *p_tf, *p_k2t, *p_k3t;
    int* p_deg;
    cudaGetSymbolAddress((void**)&p_u, g_u);
    cudaGetSymbolAddress((void**)&p_S, g_S);
    cudaGetSymbolAddress((void**)&p_h, g_h);
    cudaGetSymbolAddress((void**)&p_dinv, g_dinv);
    cudaGetSymbolAddress((void**)&p_deg, g_deg);
    cudaGetSymbolAddress((void**)&p_g, g_g);
    cudaGetSymbolAddress((void**)&p_gh, g_gh);
    cudaGetSymbolAddress((void**)&p_c, g_c);
    cudaGetSymbolAddress((void**)&p_c1, g_c1);
    cudaGetSymbolAddress((void**)&p_c2, g_c2);
    cudaGetSymbolAddress((void**)&p_tf, g_tf);
    cudaGetSymbolAddress((void**)&p_k2t, g_k2t);
    cudaGetSymbolAddress((void**)&p_k3t, g_k3t);

    // degrees -> dinv
    k_zero_i<<<cdiv(NN, 256), 256>>>(p_deg, NN);
    k_degree<<<cdiv(NE, 256), 256>>>(dst, p_deg);
    k_dinv<<<cdiv(NN, 256), 256>>>(p_deg, p_dinv);

    // GCN layer 1: F 78->78 (pad 80)
    {
        dim3 grd(cdiv(80, 64), cdiv(NN, 64));
        k_gemm<<<grd, 256>>>(x, 78, W1, nullptr, p_dinv, p_u, 80, NN, 78, 78, 80, 0);
        k_zero_f4<<<cdiv((long)NN * 80 / 4, 256), 256>>>((float4*)p_S, NN * 80 / 4);
        k_scatter<20><<<cdiv((long)NE * 20, 256), 256>>>(p_u, p_S, src, dst);
        k_combine<<<cdiv((long)NN * 78, 256), 256>>>(p_u, p_S, p_dinv, b1, p_h, 78, 80);
    }
    // GCN layer 2: 78->156
    {
        dim3 grd(cdiv(156, 64), cdiv(NN, 64));
        k_gemm<<<grd, 256>>>(p_h, 80, W2, nullptr, p_dinv, p_u, 156, NN, 78, 156, 156, 0);
        k_zero_f4<<<cdiv((long)NN * 156 / 4, 256), 256>>>((float4*)p_S, NN * 156 / 4);
        k_scatter<39><<<cdiv((long)NE * 39, 256), 256>>>(p_u, p_S, src, dst);
        k_combine<<<cdiv((long)NN * 156, 256), 256>>>(p_u, p_S, p_dinv, b2, p_h, 156, 156);
    }
    // GCN layer 3: 156->312
    {
        dim3 grd(cdiv(312, 64), cdiv(NN, 64));
        k_gemm<<<grd, 256>>>(p_h, 156, W3, nullptr, p_dinv, p_u, 312, NN, 156, 312, 312, 0);
        k_zero_f4<<<cdiv((long)NN * 312 / 4, 256), 256>>>((float4*)p_S, NN * 312 / 4);
        k_scatter<78><<<cdiv((long)NE * 78, 256), 256>>>(p_u, p_S, src, dst);
        k_combine<<<cdiv((long)NN * 312, 256), 256>>>(p_u, p_S, p_dinv, b3, p_h, 312, 312);
    }

    // graph max pool + graph MLP -> cfeat[:,0:128]
    k_segmax<<<NB, 128>>>(p_h, p_g);
    {
        dim3 grd(cdiv(1024, 64), cdiv(NB, 64));
        k_gemm<<<grd, 256>>>(p_g, 312, Wg1, bg1, nullptr, p_gh, 1024, NB, 312, 1024, 1024, 1);
    }
    {
        dim3 grd(cdiv(128, 64), cdiv(NB, 64));
        k_gemm<<<grd, 256>>>(p_gh, 1024, Wg2, bg2, nullptr, p_c, 256, NB, 1024, 128, 128, 0);
    }

    // conv tower -> tf, then FC -> cfeat[:,128:256]
    k_tr_k2<<<cdiv(64 * 32 * 8, 256), 256>>>(k2, p_k2t);
    k_tr_k3<<<cdiv(128 * 64 * 8, 256), 256>>>(k3, p_k3t);
    cudaFuncSetAttribute(k_conv, cudaFuncAttributeMaxDynamicSharedMemorySize, 12736 * 4);
    k_conv<<<NB, 256, 12736 * 4>>>(xo, k1, kb1, p_k2t, kb2, p_k3t, kb3, p_tf);
    {
        dim3 grd(cdiv(128, 64), cdiv(NB, 64));
        k_gemm<<<grd, 256>>>(p_tf, 2944, Wxt, bxt, nullptr, p_c + 128, 256, NB, 2944, 128, 128, 0);
    }

    // head
    {
        dim3 grd(cdiv(1024, 64), cdiv(NB, 64));
        k_gemm<<<grd, 256>>>(p_c, 256, Wf1, bf1, nullptr, p_c1, 1024, NB, 256, 1024, 1024, 1);
    }
    {
        dim3 grd(cdiv(128, 64), cdiv(NB, 64));
        k_gemm<<<grd, 256>>>(p_c1, 1024, Wf2, bf2, nullptr, p_c2, 128, NB, 1024, 128, 128, 1);
    }
    k_out<<<cdiv(NB * 32, 256), 256>>>(p_c2, Wo, bo, out);
}

// round 2
// speedup vs baseline: 1.2010x; 1.2010x over previous
#include <cuda_runtime.h>
#include <cstdint>

#define NN 163840
#define NE 2621440
#define NB 4096
#define NPG 40          // nodes per graph

// ---------------- device scratch (static, no allocations) ----------------
__device__ float g_u[NN * 312];      // v buffers (ping)
__device__ float g_S[NN * 312];      // scatter accumulator
__device__ float g_h[NN * 312];      // v buffers (pong) / h3
__device__ float g_dinv[NN];
__device__ int   g_deg[NN];
__device__ float g_g[NB * 312];      // graph max-pool
__device__ float g_gh[NB * 1024];
__device__ float g_c[NB * 256];      // concat [g2 | t]
__device__ float g_c1[NB * 1024];
__device__ float g_c2[NB * 128];
__device__ float g_tf[NB * 2944];    // flattened conv features
__device__ float g_k2t[32 * 8 * 64];   // k2 transposed to [ic][tap][oc]
__device__ float g_k3t[64 * 8 * 128];  // k3 transposed to [ic][tap][oc]

// ---------------- small utility kernels ----------------
__global__ void k_zero_f4(float4* p, int n4) {
    int i = blockIdx.x * blockDim.x + threadIdx.x;
    if (i < n4) p[i] = make_float4(0.f, 0.f, 0.f, 0.f);
}
__global__ void k_zero_i(int* p, int n) {
    int i = blockIdx.x * blockDim.x + threadIdx.x;
    if (i < n) p[i] = 0;
}
__global__ void k_degree(const int* __restrict__ dst, int* __restrict__ deg) {
    int e = blockIdx.x * blockDim.x + threadIdx.x;
    if (e < NE) atomicAdd(&deg[dst[e]], 1);
}
__global__ void k_dinv(const int* __restrict__ deg, float* __restrict__ dinv) {
    int i = blockIdx.x * blockDim.x + threadIdx.x;
    if (i < NN) dinv[i] = rsqrtf((float)deg[i] + 1.0f);
}
// v1[i,f] = x[i,f]*dinv[i], pad cols [78,80) with 0
__global__ void k_scale_pad(const float* __restrict__ x, const float* __restrict__ dinv,
                            float* __restrict__ v) {
    int idx = blockIdx.x * blockDim.x + threadIdx.x;
    if (idx >= NN * 80) return;
    int i = idx / 80, f = idx - i * 80;
    v[idx] = (f < 78) ? x[i * 78 + f] * dinv[i] : 0.f;
}

// ---------------- TF32 tensor-core GEMM ----------------
// C[m,n] = relu?( rowScale[m]*(A1+A2)[m,:] @ W[:,n] + bias[n] ) * outScale[m]
// writes cols [0,Npad): cols >= N get 0.  BM=128, BN=64, BK=32, 256 threads.
__device__ __forceinline__ uint32_t f2tf32(float f) {
    uint32_t u;
    asm("cvt.rna.tf32.f32 %0, %1;" : "=r"(u) : "f"(f));
    return u;
}
__global__ void __launch_bounds__(256, 2)
k_gemm_tc(const float* __restrict__ A1, const float* __restrict__ A2,
          const float* __restrict__ rowScale, int lda,
          const float* __restrict__ W, const float* __restrict__ bias,
          const float* __restrict__ outScale,
          float* __restrict__ C, int ldc,
          int M, int K, int N, int Npad, int doRelu)
{
    __shared__ uint32_t As[128][36];   // [m][k] tf32 bits, pad 4
    __shared__ uint32_t Bs[32][72];    // [k][n] tf32 bits, pad 8

    int tid = threadIdx.x;
    int lane = tid & 31;
    int warp = tid >> 5;
    int warpM = warp & 3;              // 4 warps in M -> 4*32=128
    int warpN = warp >> 2;             // 2 warps in N -> 2*32=64
    int gid = lane >> 2, tig = lane & 3;
    int rowBase = blockIdx.y * 128;
    int colBase = blockIdx.x * 64;

    float acc[2][4][4];
#pragma unroll
    for (int mt = 0; mt < 2; mt++)
#pragma unroll
        for (int nt = 0; nt < 4; nt++)
#pragma unroll
            for (int r = 0; r < 4; r++) acc[mt][nt][r] = 0.f;

    for (int kt = 0; kt < K; kt += 32) {
        // load A tile (+optional add + rowScale), convert to tf32
#pragma unroll
        for (int l = 0; l < 16; l++) {
            int idx = tid + l * 256;
            int ml = idx >> 5, kl = idx & 31;
            int m = rowBase + ml, k = kt + kl;
            float v = 0.f;
            if (m < M && k < K) {
                long off = (long)m * lda + k;
                v = A1[off];
                if (A2) v += A2[off];
                if (rowScale) v *= rowScale[m];
            }
            As[ml][kl] = f2tf32(v);
        }
        // load W tile
#pragma unroll
        for (int l = 0; l < 8; l++) {
            int idx = tid + l * 256;
            int kl = idx >> 6, nl = idx & 63;
            int k = kt + kl, n = colBase + nl;
            float v = 0.f;
            if (k < K && n < N) v = W[(long)k * N + n];
            Bs[kl][nl] = f2tf32(v);
        }
        __syncthreads();

#pragma unroll
        for (int ks = 0; ks < 4; ks++) {
            int k0 = ks * 8;
            uint32_t a[2][4];
#pragma unroll
            for (int mt = 0; mt < 2; mt++) {
                int rb = warpM * 32 + mt * 16;
                a[mt][0] = As[rb + gid][k0 + tig];
                a[mt][1] = As[rb + gid + 8][k0 + tig];
                a[mt][2] = As[rb + gid][k0 + tig + 4];
                a[mt][3] = As[rb + gid + 8][k0 + tig + 4];
            }
            uint32_t b[4][2];
#pragma unroll
            for (int nt = 0; nt < 4; nt++) {
                int nb = warpN * 32 + nt * 8 + gid;
                b[nt][0] = Bs[k0 + tig][nb];
                b[nt][1] = Bs[k0 + tig + 4][nb];
            }
#pragma unroll
            for (int mt = 0; mt < 2; mt++)
#pragma unroll
                for (int nt = 0; nt < 4; nt++) {
                    asm volatile(
                        "mma.sync.aligned.m16n8k8.row.col.f32.tf32.tf32.f32 "
                        "{%0,%1,%2,%3}, {%4,%5,%6,%7}, {%8,%9}, {%0,%1,%2,%3};"
                        : "+f"(acc[mt][nt][0]), "+f"(acc[mt][nt][1]),
                          "+f"(acc[mt][nt][2]), "+f"(acc[mt][nt][3])
                        : "r"(a[mt][0]), "r"(a[mt][1]), "r"(a[mt][2]), "r"(a[mt][3]),
                          "r"(b[nt][0]), "r"(b[nt][1]));
                }
        }
        __syncthreads();
    }

    // epilogue
#pragma unroll
    for (int mt = 0; mt < 2; mt++) {
#pragma unroll
        for (int nt = 0; nt < 4; nt++) {
#pragma unroll
            for (int r = 0; r < 4; r++) {
                int m = rowBase + warpM * 32 + mt * 16 + gid + ((r >= 2) ? 8 : 0);
                int n = colBase + warpN * 32 + nt * 8 + 2 * tig + (r & 1);
                if (m >= M || n >= Npad) continue;
                float v = 0.f;
                if (n < N) {
                    v = acc[mt][nt][r];
                    if (bias) v += bias[n];
                    if (doRelu) v = fmaxf(v, 0.f);
                    if (outScale) v *= outScale[m];
                }
                C[(long)m * ldc + n] = v;
            }
        }
    }
}

// ---------------- edge scatter: S[dst] += v[src]  (v4 reductions) ----------------
template <int CH>   // CH = padded_feature_dim / 4
__global__ void k_scatter(const float* __restrict__ v, float* __restrict__ S,
                          const int* __restrict__ src, const int* __restrict__ dst)
{
    long idx = (long)blockIdx.x * blockDim.x + threadIdx.x;
    if (idx >= (long)NE * CH) return;
    int e = (int)(idx / CH);
    int c = (int)(idx - (long)e * CH);
    int s = src[e], d = dst[e];
    const int stride = CH * 4;
    float4 w = *(const float4*)(v + (long)s * stride + c * 4);
    float* p = S + (long)d * stride + c * 4;
    asm volatile("red.global.add.v4.f32 [%0], {%1, %2, %3, %4};"
                 :: "l"(p), "f"(w.x), "f"(w.y), "f"(w.z), "f"(w.w) : "memory");
}

// per-graph max pool over 40 contiguous nodes, F=312 stride 312
__global__ void k_segmax(const float* __restrict__ h, float* __restrict__ g)
{
    int b = blockIdx.x;
    const float* p = h + (long)b * NPG * 312;
    for (int f = threadIdx.x; f < 312; f += blockDim.x) {
        float m = -3.4e38f;
#pragma unroll 4
        for (int n = 0; n < NPG; n++) m = fmaxf(m, p[n * 312 + f]);
        g[b * 312 + f] = m;
    }
}

// ---------------- conv weight transposes ----------------
__global__ void k_tr_k2(const float* __restrict__ k2, float* __restrict__ k2t) {
    int idx = blockIdx.x * blockDim.x + threadIdx.x;
    if (idx >= 64 * 32 * 8) return;
    int oc = idx >> 8, r = idx & 255, ic = r >> 3, i = r & 7;
    k2t[(ic * 8 + i) * 64 + oc] = k2[idx];
}
__global__ void k_tr_k3(const float* __restrict__ k3, float* __restrict__ k3t) {
    int idx = blockIdx.x * blockDim.x + threadIdx.x;
    if (idx >= 128 * 64 * 8) return;
    int oc = idx >> 9, r = idx & 511, ic = r >> 3, i = r & 7;
    k3t[(ic * 8 + i) * 128 + oc] = k3[idx];
}

// ---------------- fused conv tower: one CTA per graph ----------------
__global__ void k_conv(const float* __restrict__ xo,
                       const float* __restrict__ k1, const float* __restrict__ kb1,
                       const float* __restrict__ k2t, const float* __restrict__ kb2,
                       const float* __restrict__ k3t, const float* __restrict__ kb3,
                       float* __restrict__ tf)
{
    extern __shared__ float sm[];
    const int S_T1 = 0, S_T2 = 7744, S_IN = 7744, S_K1 = 8480, S_KB1 = 8736, S_T3 = 0;
    int b = blockIdx.x;
    int tid = threadIdx.x;

    for (int i = tid; i < 735; i += 256) sm[S_IN + i] = xo[(long)b * 735 + i];
    if (tid < 256) sm[S_K1 + tid] = k1[tid];
    if (tid < 32)  sm[S_KB1 + tid] = kb1[tid];
    __syncthreads();

    // stage 1: conv(1->32,k8) + relu + pool3 -> t1[32][242]
    for (int o = tid; o < 32 * 242; o += 256) {
        int ch = o / 242;
        int p = o - ch * 242;
        int base = 3 * p;
        const float* w = &sm[S_K1 + ch * 8];
        float s0 = 0.f, s1 = 0.f, s2 = 0.f;
#pragma unroll
        for (int i = 0; i < 8; i++) {
            float wv = w[i];
            s0 = fmaf(sm[S_IN + base + i],     wv, s0);
            s1 = fmaf(sm[S_IN + base + 1 + i], wv, s1);
            s2 = fmaf(sm[S_IN + base + 2 + i], wv, s2);
        }
        float m = fmaxf(fmaxf(s0, s1), s2) + sm[S_KB1 + ch];
        sm[S_T1 + o] = fmaxf(m, 0.f);
    }
    __syncthreads();

    // stage 2: conv(32->64,k8) + relu + pool3 -> t2[64][78]
    {
        int oc = tid & 63;
        int pt = tid >> 6;
        float bb = kb2[oc];
        for (int c4 = 0; c4 < 5; c4++) {
            int p0 = pt * 20 + c4 * 4;
            int q0 = 3 * p0;
            float acc[12];
#pragma unroll
            for (int r = 0; r < 12; r++) acc[r] = 0.f;
            for (int ic = 0; ic < 32; ic++) {
                float w[8];
#pragma unroll
                for (int i = 0; i < 8; i++) w[i] = k2t[(ic * 8 + i) * 64 + oc];
                const float* t1r = &sm[S_T1 + ic * 242];
                float inb[19];
#pragma unroll
                for (int i = 0; i < 19; i++) {
                    int q = q0 + i;
                    inb[i] = t1r[q < 242 ? q : 241];
                }
#pragma unroll
                for (int r = 0; r < 12; r++)
#pragma unroll
                    for (int i = 0; i < 8; i++)
                        acc[r] = fmaf(inb[r + i], w[i], acc[r]);
            }
#pragma unroll
            for (int pp = 0; pp < 4; pp++) {
                int p = p0 + pp;
                if (p < 78) {
                    float m = fmaxf(fmaxf(acc[3 * pp], acc[3 * pp + 1]), acc[3 * pp + 2]) + bb;
                    sm[S_T2 + oc * 78 + p] = fmaxf(m, 0.f);
                }
            }
        }
    }
    __syncthreads();

    // stage 3: conv(64->128,k8) + relu + pool3 -> t3[128][23]
    {
        int oc = tid & 127;
        int pt = tid >> 7;
        float bb = kb3[oc];
        for (int c4 = 0; c4 < 3; c4++) {
            int p0 = pt * 12 + c4 * 4;
            int q0 = 3 * p0;
            float acc[12];
#pragma unroll
            for (int r = 0; r < 12; r++) acc[r] = 0.f;
            for (int ic = 0; ic < 64; ic++) {
                float w[8];
#pragma unroll
                for (int i = 0; i < 8; i++) w[i] = k3t[(ic * 8 + i) * 128 + oc];
                const float* t2r = &sm[S_T2 + ic * 78];
                float inb[19];
#pragma unroll
                for (int i = 0; i < 19; i++) {
                    int q = q0 + i;
                    inb[i] = t2r[q < 78 ? q : 77];
                }
#pragma unroll
                for (int r = 0; r < 12; r++)
#pragma unroll
                    for (int i = 0; i < 8; i++)
                        acc[r] = fmaf(inb[r + i], w[i], acc[r]);
            }
#pragma unroll
            for (int pp = 0; pp < 4; pp++) {
                int p = p0 + pp;
                if (p < 23) {
                    float m = fmaxf(fmaxf(acc[3 * pp], acc[3 * pp + 1]), acc[3 * pp + 2]) + bb;
                    sm[S_T3 + oc * 23 + p] = fmaxf(m, 0.f);
                }
            }
        }
    }
    __syncthreads();

    for (int i = tid; i < 2944; i += 256) tf[(long)b * 2944 + i] = sm[S_T3 + i];
}

// final dot: out[b] = c2[b,:] . Wo + bo
__global__ void k_out(const float* __restrict__ c2, const float* __restrict__ Wo,
                      const float* __restrict__ bo, float* __restrict__ out)
{
    int warp = (blockIdx.x * blockDim.x + threadIdx.x) >> 5;
    int lane = threadIdx.x & 31;
    if (warp >= NB) return;
    float s = 0.f;
#pragma unroll
    for (int i = lane; i < 128; i += 32) s = fmaf(c2[warp * 128 + i], Wo[i], s);
#pragma unroll
    for (int off = 16; off; off >>= 1) s += __shfl_down_sync(0xffffffffu, s, off);
    if (lane == 0) out[warp] = s + bo[0];
}

// ---------------- launch ----------------
static inline int cdiv(long a, long b) { return (int)((a + b - 1) / b); }

extern "C" void kernel_launch(void* const* d_in, const int* in_sizes, int n_in,
                              void* d_out, int out_size)
{
    const float* x    = (const float*)d_in[0];
    const int*   ei   = (const int*)d_in[1];
    const float* xo   = (const float*)d_in[3];
    const float* W1   = (const float*)d_in[4];  const float* b1  = (const float*)d_in[5];
    const float* W2   = (const float*)d_in[6];  const float* b2  = (const float*)d_in[7];
    const float* W3   = (const float*)d_in[8];  const float* b3  = (const float*)d_in[9];
    const float* Wg1  = (const float*)d_in[10]; const float* bg1 = (const float*)d_in[11];
    const float* Wg2  = (const float*)d_in[12]; const float* bg2 = (const float*)d_in[13];
    const float* k1   = (const float*)d_in[14]; const float* kb1 = (const float*)d_in[15];
    const float* k2   = (const float*)d_in[16]; const float* kb2 = (const float*)d_in[17];
    const float* k3   = (const float*)d_in[18]; const float* kb3 = (const float*)d_in[19];
    const float* Wxt  = (const float*)d_in[20]; const float* bxt = (const float*)d_in[21];
    const float* Wf1  = (const float*)d_in[22]; const float* bf1 = (const float*)d_in[23];
    const float* Wf2  = (const float*)d_in[24]; const float* bf2 = (const float*)d_in[25];
    const float* Wo   = (const float*)d_in[26]; const float* bo  = (const float*)d_in[27];
    const int* src = ei;
    const int* dst = ei + NE;
    float* out = (float*)d_out;

    float *p_u, *p_S, *p_h, *p_dinv, *p_g, *p_gh, *p_c, *p_c1, *p_c2, *p_tf, *p_k2t, *p_k3t;
    int* p_deg;
    cudaGetSymbolAddress((void**)&p_u, g_u);
    cudaGetSymbolAddress((void**)&p_S, g_S);
    cudaGetSymbolAddress((void**)&p_h, g_h);
    cudaGetSymbolAddress((void**)&p_dinv, g_dinv);
    cudaGetSymbolAddress((void**)&p_deg, g_deg);
    cudaGetSymbolAddress((void**)&p_g, g_g);
    cudaGetSymbolAddress((void**)&p_gh, g_gh);
    cudaGetSymbolAddress((void**)&p_c, g_c);
    cudaGetSymbolAddress((void**)&p_c1, g_c1);
    cudaGetSymbolAddress((void**)&p_c2, g_c2);
    cudaGetSymbolAddress((void**)&p_tf, g_tf);
    cudaGetSymbolAddress((void**)&p_k2t, g_k2t);
    cudaGetSymbolAddress((void**)&p_k3t, g_k3t);

    // degrees -> dinv
    k_zero_i<<<cdiv(NN, 256), 256>>>(p_deg, NN);
    k_degree<<<cdiv(NE, 256), 256>>>(dst, p_deg);
    k_dinv<<<cdiv(NN, 256), 256>>>(p_deg, p_dinv);

    // v1 = x * dinv (padded to 80 cols)
    k_scale_pad<<<cdiv((long)NN * 80, 256), 256>>>(x, p_dinv, p_u);

    // ---- GCN layer 1: aggregate(78ch) then GEMM 78->78, out v2 = relu(.)*dinv ----
    k_zero_f4<<<cdiv((long)NN * 80 / 4, 256), 256>>>((float4*)p_S, NN * 80 / 4);
    k_scatter<20><<<cdiv((long)NE * 20, 256), 256>>>(p_u, p_S, src, dst);
    {
        dim3 grd(cdiv(80, 64), cdiv(NN, 128));
        k_gemm_tc<<<grd, 256>>>(p_S, p_u, p_dinv, 80, W1, b1, p_dinv,
                                p_h, 80, NN, 78, 78, 80, 1);
    }
    // ---- GCN layer 2: aggregate(78ch) then GEMM 78->156, out v3 = relu(.)*dinv ----
    k_zero_f4<<<cdiv((long)NN * 80 / 4, 256), 256>>>((float4*)p_S, NN * 80 / 4);
    k_scatter<20><<<cdiv((long)NE * 20, 256), 256>>>(p_h, p_S, src, dst);
    {
        dim3 grd(cdiv(156, 64), cdiv(NN, 128));
        k_gemm_tc<<<grd, 256>>>(p_S, p_h, p_dinv, 80, W2, b2, p_dinv,
                                p_u, 156, NN, 78, 156, 156, 1);
    }
    // ---- GCN layer 3: aggregate(156ch) then GEMM 156->312, out h3 ----
    k_zero_f4<<<cdiv((long)NN * 156 / 4, 256), 256>>>((float4*)p_S, NN * 156 / 4);
    k_scatter<39><<<cdiv((long)NE * 39, 256), 256>>>(p_u, p_S, src, dst);
    {
        dim3 grd(cdiv(312, 64), cdiv(NN, 128));
        k_gemm_tc<<<grd, 256>>>(p_S, p_u, p_dinv, 156, W3, b3, nullptr,
                                p_h, 312, NN, 156, 312, 312, 1);
    }

    // graph max pool + graph MLP -> c[:,0:128]
    k_segmax<<<NB, 128>>>(p_h, p_g);
    {
        dim3 grd(cdiv(1024, 64), cdiv(NB, 128));
        k_gemm_tc<<<grd, 256>>>(p_g, nullptr, nullptr, 312, Wg1, bg1, nullptr,
                                p_gh, 1024, NB, 312, 1024, 1024, 1);
    }
    {
        dim3 grd(cdiv(128, 64), cdiv(NB, 128));
        k_gemm_tc<<<grd, 256>>>(p_gh, nullptr, nullptr, 1024, Wg2, bg2, nullptr,
                                p_c, 256, NB, 1024, 128, 128, 0);
    }

    // conv tower -> tf, then FC -> c[:,128:256]
    k_tr_k2<<<cdiv(64 * 32 * 8, 256), 256>>>(k2, p_k2t);
    k_tr_k3<<<cdiv(128 * 64 * 8, 256), 256>>>(k3, p_k3t);
    cudaFuncSetAttribute(k_conv, cudaFuncAttributeMaxDynamicSharedMemorySize, 12736 * 4);
    k_conv<<<NB, 256, 12736 * 4>>>(xo, k1, kb1, p_k2t, kb2, p_k3t, kb3, p_tf);
    {
        dim3 grd(cdiv(128, 64), cdiv(NB, 128));
        k_gemm_tc<<<grd, 256>>>(p_tf, nullptr, nullptr, 2944, Wxt, bxt, nullptr,
                                p_c + 128, 256, NB, 2944, 128, 128, 0);
    }

    // head
    {
        dim3 grd(cdiv(1024, 64), cdiv(NB, 128));
        k_gemm_tc<<<grd, 256>>>(p_c, nullptr, nullptr, 256, Wf1, bf1, nullptr,
                                p_c1, 1024, NB, 256, 1024, 1024, 1);
    }
    {
        dim3 grd(cdiv(128, 64), cdiv(NB, 128));
        k_gemm_tc<<<grd, 256>>>(p_c1, nullptr, nullptr, 1024, Wf2, bf2, nullptr,
                                p_c2, 128, NB, 1024, 128, 128, 1);
    }
    k_out<<<cdiv(NB * 32, 256), 256>>>(p_c2, Wo, bo, out);
}

// round 3
// speedup vs baseline: 1.7232x; 1.4348x over previous
#include <cuda_runtime.h>
#include <cstdint>

#define NN 163840
#define NE 2621440
#define NB 4096
#define NPG 40          // nodes per graph
#define NBLK 160        // NN / 1024

// ---------------- device scratch (static, no allocations) ----------------
__device__ float g_u[NN * 312];      // v buffers (ping)
__device__ float g_S[NN * 312];      // aggregation output
__device__ float g_h[NN * 312];      // v buffers (pong) / h3
__device__ float g_dinv[NN];
__device__ int   g_deg[NN];
__device__ int   g_rowptr[NN + 1];
__device__ int   g_pos[NN];
__device__ int   g_csr[NE];
__device__ int   g_bsum[NBLK];
__device__ float g_g[NB * 312];      // graph max-pool
__device__ float g_gh[NB * 1024];
__device__ float g_c[NB * 256];      // concat [g2 | t]
__device__ float g_c1[NB * 1024];
__device__ float g_c2[NB * 128];
__device__ float g_tf[NB * 2944];    // flattened conv features
__device__ float g_k2t[32 * 8 * 64];   // k2 transposed to [ic][tap][oc]
__device__ float g_k3t[64 * 8 * 128];  // k3 transposed to [ic][tap][oc]

// ---------------- small utility kernels ----------------
__global__ void k_zero_i(int* p, int n) {
    int i = blockIdx.x * blockDim.x + threadIdx.x;
    if (i < n) p[i] = 0;
}
__global__ void k_degree(const int* __restrict__ dst, int* __restrict__ deg) {
    int e = blockIdx.x * blockDim.x + threadIdx.x;
    if (e < NE) atomicAdd(&deg[dst[e]], 1);
}
__global__ void k_dinv(const int* __restrict__ deg, float* __restrict__ dinv) {
    int i = blockIdx.x * blockDim.x + threadIdx.x;
    if (i < NN) dinv[i] = rsqrtf((float)deg[i] + 1.0f);
}
// v1[i,f] = x[i,f]*dinv[i], pad cols [78,80) with 0
__global__ void k_scale_pad(const float* __restrict__ x, const float* __restrict__ dinv,
                            float* __restrict__ v) {
    int idx = blockIdx.x * blockDim.x + threadIdx.x;
    if (idx >= NN * 80) return;
    int i = idx / 80, f = idx - i * 80;
    v[idx] = (f < 78) ? x[i * 78 + f] * dinv[i] : 0.f;
}

// ---------------- CSR build: exclusive scan of deg + edge fill ----------------
__global__ void k_scan_block(const int* __restrict__ deg, int* __restrict__ rowptr,
                             int* __restrict__ bsum) {
    __shared__ int sm[256];
    int b = blockIdx.x, t = threadIdx.x;
    int base = b * 1024 + t * 4;
    int d0 = deg[base], d1 = deg[base + 1], d2 = deg[base + 2], d3 = deg[base + 3];
    int s = d0 + d1 + d2 + d3;
    sm[t] = s;
    __syncthreads();
    for (int off = 1; off < 256; off <<= 1) {
        int v2 = (t >= off) ? sm[t - off] : 0;
        __syncthreads();
        sm[t] += v2;
        __syncthreads();
    }
    int excl = sm[t] - s;
    rowptr[base] = excl;
    rowptr[base + 1] = excl + d0;
    rowptr[base + 2] = excl + d0 + d1;
    rowptr[base + 3] = excl + d0 + d1 + d2;
    if (t == 255) bsum[b] = sm[255];
}
__global__ void k_scan_bsum(int* __restrict__ bsum) {
    __shared__ int sm[256];
    int t = threadIdx.x;
    int v = (t < NBLK) ? bsum[t] : 0;
    sm[t] = v;
    __syncthreads();
    for (int off = 1; off < 256; off <<= 1) {
        int v2 = (t >= off) ? sm[t - off] : 0;
        __syncthreads();
        sm[t] += v2;
        __syncthreads();
    }
    if (t < NBLK) bsum[t] = sm[t] - v;
}
__global__ void k_scan_add(int* __restrict__ rowptr, const int* __restrict__ bsum,
                           int* __restrict__ pos) {
    int i = blockIdx.x * blockDim.x + threadIdx.x;
    if (i < NN) {
        int r = rowptr[i] + bsum[i >> 10];
        rowptr[i] = r;
        pos[i] = r;
    }
    if (i == 0) rowptr[NN] = NE;
}
__global__ void k_fill(const int* __restrict__ src, const int* __restrict__ dst,
                       int* __restrict__ pos, int* __restrict__ csr) {
    int e = blockIdx.x * blockDim.x + threadIdx.x;
    if (e >= NE) return;
    int slot = atomicAdd(&pos[dst[e]], 1);
    csr[slot] = src[e];
}

// ---------------- CSR gather aggregation: S[n] = v[n] + sum_{e in adj(n)} v[src] ----
template <int CH>   // CH = padded_feature_dim / 4
__global__ void k_gather(const float* __restrict__ v, float* __restrict__ S,
                         const int* __restrict__ rowptr, const int* __restrict__ csr)
{
    long idx = (long)blockIdx.x * blockDim.x + threadIdx.x;
    if (idx >= (long)NN * CH) return;
    int n = (int)(idx / CH);
    int c = (int)(idx - (long)n * CH);
    const float4* vp = (const float4*)v;
    float4 acc = vp[(long)n * CH + c];
    int e = rowptr[n], end = rowptr[n + 1];
    for (; e < end; e++) {
        int s = csr[e];
        float4 w = __ldg(&vp[(long)s * CH + c]);
        acc.x += w.x; acc.y += w.y; acc.z += w.z; acc.w += w.w;
    }
    ((float4*)S)[(long)n * CH + c] = acc;
}

// ---------------- TF32 tensor-core GEMM ----------------
// C[m,n] = relu?( rowScale[m]*A[m,:] @ W[:,n] + bias[n] ) * outScale[m]
__device__ __forceinline__ uint32_t f2tf32(float f) {
    uint32_t u;
    asm("cvt.rna.tf32.f32 %0, %1;" : "=r"(u) : "f"(f));
    return u;
}
__global__ void __launch_bounds__(256, 2)
k_gemm_tc(const float* __restrict__ A1,
          const float* __restrict__ rowScale, int lda,
          const float* __restrict__ W, const float* __restrict__ bias,
          const float* __restrict__ outScale,
          float* __restrict__ C, int ldc,
          int M, int K, int N, int Npad, int doRelu)
{
    __shared__ uint32_t As[128][36];   // [m][k] tf32 bits, pad 4
    __shared__ uint32_t Bs[32][72];    // [k][n] tf32 bits, pad 8

    int tid = threadIdx.x;
    int lane = tid & 31;
    int warp = tid >> 5;
    int warpM = warp & 3;
    int warpN = warp >> 2;
    int gid = lane >> 2, tig = lane & 3;
    int rowBase = blockIdx.y * 128;
    int colBase = blockIdx.x * 64;

    float acc[2][4][4];
#pragma unroll
    for (int mt = 0; mt < 2; mt++)
#pragma unroll
        for (int nt = 0; nt < 4; nt++)
#pragma unroll
            for (int r = 0; r < 4; r++) acc[mt][nt][r] = 0.f;

    for (int kt = 0; kt < K; kt += 32) {
#pragma unroll
        for (int l = 0; l < 16; l++) {
            int idx = tid + l * 256;
            int ml = idx >> 5, kl = idx & 31;
            int m = rowBase + ml, k = kt + kl;
            float v = 0.f;
            if (m < M && k < K) {
                v = A1[(long)m * lda + k];
                if (rowScale) v *= rowScale[m];
            }
            As[ml][kl] = f2tf32(v);
        }
#pragma unroll
        for (int l = 0; l < 8; l++) {
            int idx = tid + l * 256;
            int kl = idx >> 6, nl = idx & 63;
            int k = kt + kl, n = colBase + nl;
            float v = 0.f;
            if (k < K && n < N) v = W[(long)k * N + n];
            Bs[kl][nl] = f2tf32(v);
        }
        __syncthreads();

#pragma unroll
        for (int ks = 0; ks < 4; ks++) {
            int k0 = ks * 8;
            uint32_t a[2][4];
#pragma unroll
            for (int mt = 0; mt < 2; mt++) {
                int rb = warpM * 32 + mt * 16;
                a[mt][0] = As[rb + gid][k0 + tig];
                a[mt][1] = As[rb + gid + 8][k0 + tig];
                a[mt][2] = As[rb + gid][k0 + tig + 4];
                a[mt][3] = As[rb + gid + 8][k0 + tig + 4];
            }
            uint32_t b[4][2];
#pragma unroll
            for (int nt = 0; nt < 4; nt++) {
                int nb = warpN * 32 + nt * 8 + gid;
                b[nt][0] = Bs[k0 + tig][nb];
                b[nt][1] = Bs[k0 + tig + 4][nb];
            }
#pragma unroll
            for (int mt = 0; mt < 2; mt++)
#pragma unroll
                for (int nt = 0; nt < 4; nt++) {
                    asm volatile(
                        "mma.sync.aligned.m16n8k8.row.col.f32.tf32.tf32.f32 "
                        "{%0,%1,%2,%3}, {%4,%5,%6,%7}, {%8,%9}, {%0,%1,%2,%3};"
                        : "+f"(acc[mt][nt][0]), "+f"(acc[mt][nt][1]),
                          "+f"(acc[mt][nt][2]), "+f"(acc[mt][nt][3])
                        : "r"(a[mt][0]), "r"(a[mt][1]), "r"(a[mt][2]), "r"(a[mt][3]),
                          "r"(b[nt][0]), "r"(b[nt][1]));
                }
        }
        __syncthreads();
    }

#pragma unroll
    for (int mt = 0; mt < 2; mt++) {
#pragma unroll
        for (int nt = 0; nt < 4; nt++) {
#pragma unroll
            for (int r = 0; r < 4; r++) {
                int m = rowBase + warpM * 32 + mt * 16 + gid + ((r >= 2) ? 8 : 0);
                int n = colBase + warpN * 32 + nt * 8 + 2 * tig + (r & 1);
                if (m >= M || n >= Npad) continue;
                float v = 0.f;
                if (n < N) {
                    v = acc[mt][nt][r];
                    if (bias) v += bias[n];
                    if (doRelu) v = fmaxf(v, 0.f);
                    if (outScale) v *= outScale[m];
                }
                C[(long)m * ldc + n] = v;
            }
        }
    }
}

// per-graph max pool over 40 contiguous nodes, F=312 stride 312
__global__ void k_segmax(const float* __restrict__ h, float* __restrict__ g)
{
    int b = blockIdx.x;
    const float* p = h + (long)b * NPG * 312;
    for (int f = threadIdx.x; f < 312; f += blockDim.x) {
        float m = -3.4e38f;
#pragma unroll 4
        for (int n = 0; n < NPG; n++) m = fmaxf(m, p[n * 312 + f]);
        g[b * 312 + f] = m;
    }
}

// ---------------- conv weight transposes ----------------
__global__ void k_tr_k2(const float* __restrict__ k2, float* __restrict__ k2t) {
    int idx = blockIdx.x * blockDim.x + threadIdx.x;
    if (idx >= 64 * 32 * 8) return;
    int oc = idx >> 8, r = idx & 255, ic = r >> 3, i = r & 7;
    k2t[(ic * 8 + i) * 64 + oc] = k2[idx];
}
__global__ void k_tr_k3(const float* __restrict__ k3, float* __restrict__ k3t) {
    int idx = blockIdx.x * blockDim.x + threadIdx.x;
    if (idx >= 128 * 64 * 8) return;
    int oc = idx >> 9, r = idx & 511, ic = r >> 3, i = r & 7;
    k3t[(ic * 8 + i) * 128 + oc] = k3[idx];
}

// ---------------- fused conv tower: one CTA per graph ----------------
__global__ void k_conv(const float* __restrict__ xo,
                       const float* __restrict__ k1, const float* __restrict__ kb1,
                       const float* __restrict__ k2t, const float* __restrict__ kb2,
                       const float* __restrict__ k3t, const float* __restrict__ kb3,
                       float* __restrict__ tf)
{
    extern __shared__ float sm[];
    const int S_T1 = 0, S_T2 = 7744, S_IN = 7744, S_K1 = 8480, S_KB1 = 8736, S_T3 = 0;
    int b = blockIdx.x;
    int tid = threadIdx.x;

    for (int i = tid; i < 735; i += 256) sm[S_IN + i] = xo[(long)b * 735 + i];
    if (tid < 256) sm[S_K1 + tid] = k1[tid];
    if (tid < 32)  sm[S_KB1 + tid] = kb1[tid];
    __syncthreads();

    // stage 1: conv(1->32,k8) + relu + pool3 -> t1[32][242]
    for (int o = tid; o < 32 * 242; o += 256) {
        int ch = o / 242;
        int p = o - ch * 242;
        int base = 3 * p;
        const float* w = &sm[S_K1 + ch * 8];
        float s0 = 0.f, s1 = 0.f, s2 = 0.f;
#pragma unroll
        for (int i = 0; i < 8; i++) {
            float wv = w[i];
            s0 = fmaf(sm[S_IN + base + i],     wv, s0);
            s1 = fmaf(sm[S_IN + base + 1 + i], wv, s1);
            s2 = fmaf(sm[S_IN + base + 2 + i], wv, s2);
        }
        float m = fmaxf(fmaxf(s0, s1), s2) + sm[S_KB1 + ch];
        sm[S_T1 + o] = fmaxf(m, 0.f);
    }
    __syncthreads();

    // stage 2: conv(32->64,k8) + relu + pool3 -> t2[64][78]
    {
        int oc = tid & 63;
        int pt = tid >> 6;
        float bb = kb2[oc];
        for (int c4 = 0; c4 < 5; c4++) {
            int p0 = pt * 20 + c4 * 4;
            int q0 = 3 * p0;
            float acc[12];
#pragma unroll
            for (int r = 0; r < 12; r++) acc[r] = 0.f;
            for (int ic = 0; ic < 32; ic++) {
                float w[8];
#pragma unroll
                for (int i = 0; i < 8; i++) w[i] = k2t[(ic * 8 + i) * 64 + oc];
                const float* t1r = &sm[S_T1 + ic * 242];
                float inb[19];
#pragma unroll
                for (int i = 0; i < 19; i++) {
                    int q = q0 + i;
                    inb[i] = t1r[q < 242 ? q : 241];
                }
#pragma unroll
                for (int r = 0; r < 12; r++)
#pragma unroll
                    for (int i = 0; i < 8; i++)
                        acc[r] = fmaf(inb[r + i], w[i], acc[r]);
            }
#pragma unroll
            for (int pp = 0; pp < 4; pp++) {
                int p = p0 + pp;
                if (p < 78) {
                    float m = fmaxf(fmaxf(acc[3 * pp], acc[3 * pp + 1]), acc[3 * pp + 2]) + bb;
                    sm[S_T2 + oc * 78 + p] = fmaxf(m, 0.f);
                }
            }
        }
    }
    __syncthreads();

    // stage 3: conv(64->128,k8) + relu + pool3 -> t3[128][23]
    {
        int oc = tid & 127;
        int pt = tid >> 7;
        float bb = kb3[oc];
        for (int c4 = 0; c4 < 3; c4++) {
            int p0 = pt * 12 + c4 * 4;
            int q0 = 3 * p0;
            float acc[12];
#pragma unroll
            for (int r = 0; r < 12; r++) acc[r] = 0.f;
            for (int ic = 0; ic < 64; ic++) {
                float w[8];
#pragma unroll
                for (int i = 0; i < 8; i++) w[i] = k3t[(ic * 8 + i) * 128 + oc];
                const float* t2r = &sm[S_T2 + ic * 78];
                float inb[19];
#pragma unroll
                for (int i = 0; i < 19; i++) {
                    int q = q0 + i;
                    inb[i] = t2r[q < 78 ? q : 77];
                }
#pragma unroll
                for (int r = 0; r < 12; r++)
#pragma unroll
                    for (int i = 0; i < 8; i++)
                        acc[r] = fmaf(inb[r + i], w[i], acc[r]);
            }
#pragma unroll
            for (int pp = 0; pp < 4; pp++) {
                int p = p0 + pp;
                if (p < 23) {
                    float m = fmaxf(fmaxf(acc[3 * pp], acc[3 * pp + 1]), acc[3 * pp + 2]) + bb;
                    sm[S_T3 + oc * 23 + p] = fmaxf(m, 0.f);
                }
            }
        }
    }
    __syncthreads();

    for (int i = tid; i < 2944; i += 256) tf[(long)b * 2944 + i] = sm[S_T3 + i];
}

// final dot: out[b] = c2[b,:] . Wo + bo
__global__ void k_out(const float* __restrict__ c2, const float* __restrict__ Wo,
                      const float* __restrict__ bo, float* __restrict__ out)
{
    int warp = (blockIdx.x * blockDim.x + threadIdx.x) >> 5;
    int lane = threadIdx.x & 31;
    if (warp >= NB) return;
    float s = 0.f;
#pragma unroll
    for (int i = lane; i < 128; i += 32) s = fmaf(c2[warp * 128 + i], Wo[i], s);
#pragma unroll
    for (int off = 16; off; off >>= 1) s += __shfl_down_sync(0xffffffffu, s, off);
    if (lane == 0) out[warp] = s + bo[0];
}

// ---------------- launch ----------------
static inline int cdiv(long a, long b) { return (int)((a + b - 1) / b); }

extern "C" void kernel_launch(void* const* d_in, const int* in_sizes, int n_in,
                              void* d_out, int out_size)
{
    const float* x    = (const float*)d_in[0];
    const int*   ei   = (const int*)d_in[1];
    const float* xo   = (const float*)d_in[3];
    const float* W1   = (const float*)d_in[4];  const float* b1  = (const float*)d_in[5];
    const float* W2   = (const float*)d_in[6];  const float* b2  = (const float*)d_in[7];
    const float* W3   = (const float*)d_in[8];  const float* b3  = (const float*)d_in[9];
    const float* Wg1  = (const float*)d_in[10]; const float* bg1 = (const float*)d_in[11];
    const float* Wg2  = (const float*)d_in[12]; const float* bg2 = (const float*)d_in[13];
    const float* k1   = (const float*)d_in[14]; const float* kb1 = (const float*)d_in[15];
    const float* k2   = (const float*)d_in[16]; const float* kb2 = (const float*)d_in[17];
    const float* k3   = (const float*)d_in[18]; const float* kb3 = (const float*)d_in[19];
    const float* Wxt  = (const float*)d_in[20]; const float* bxt = (const float*)d_in[21];
    const float* Wf1  = (const float*)d_in[22]; const float* bf1 = (const float*)d_in[23];
    const float* Wf2  = (const float*)d_in[24]; const float* bf2 = (const float*)d_in[25];
    const float* Wo   = (const float*)d_in[26]; const float* bo  = (const float*)d_in[27];
    const int* src = ei;
    const int* dst = ei + NE;
    float* out = (float*)d_out;

    float *p_u, *p_S, *p_h, *p_dinv, *p_g, *p_gh, *p_c, *p_c1, *p_c2, *p_tf, *p_k2t, *p_k3t;
    int *p_deg, *p_rowptr, *p_pos, *p_csr, *p_bsum;
    cudaGetSymbolAddress((void**)&p_u, g_u);
    cudaGetSymbolAddress((void**)&p_S, g_S);
    cudaGetSymbolAddress((void**)&p_h, g_h);
    cudaGetSymbolAddress((void**)&p_dinv, g_dinv);
    cudaGetSymbolAddress((void**)&p_deg, g_deg);
    cudaGetSymbolAddress((void**)&p_rowptr, g_rowptr);
    cudaGetSymbolAddress((void**)&p_pos, g_pos);
    cudaGetSymbolAddress((void**)&p_csr, g_csr);
    cudaGetSymbolAddress((void**)&p_bsum, g_bsum);
    cudaGetSymbolAddress((void**)&p_g, g_g);
    cudaGetSymbolAddress((void**)&p_gh, g_gh);
    cudaGetSymbolAddress((void**)&p_c, g_c);
    cudaGetSymbolAddress((void**)&p_c1, g_c1);
    cudaGetSymbolAddress((void**)&p_c2, g_c2);
    cudaGetSymbolAddress((void**)&p_tf, g_tf);
    cudaGetSymbolAddress((void**)&p_k2t, g_k2t);
    cudaGetSymbolAddress((void**)&p_k3t, g_k3t);

    // degrees -> dinv ; CSR build
    k_zero_i<<<cdiv(NN, 256), 256>>>(p_deg, NN);
    k_degree<<<cdiv(NE, 256), 256>>>(dst, p_deg);
    k_dinv<<<cdiv(NN, 256), 256>>>(p_deg, p_dinv);
    k_scan_block<<<NBLK, 256>>>(p_deg, p_rowptr, p_bsum);
    k_scan_bsum<<<1, 256>>>(p_bsum);
    k_scan_add<<<cdiv(NN, 256), 256>>>(p_rowptr, p_bsum, p_pos);
    k_fill<<<cdiv(NE, 256), 256>>>(src, dst, p_pos, p_csr);

    // v1 = x * dinv (padded to 80 cols)
    k_scale_pad<<<cdiv((long)NN * 80, 256), 256>>>(x, p_dinv, p_u);

    // ---- GCN layer 1: gather(80ch) then GEMM 78->78, out v2 = relu(.)*dinv ----
    k_gather<20><<<cdiv((long)NN * 20, 256), 256>>>(p_u, p_S, p_rowptr, p_csr);
    {
        dim3 grd(cdiv(80, 64), cdiv(NN, 128));
        k_gemm_tc<<<grd, 256>>>(p_S, p_dinv, 80, W1, b1, p_dinv,
                                p_h, 80, NN, 78, 78, 80, 1);
    }
    // ---- GCN layer 2: gather(80ch) then GEMM 78->156, out v3 = relu(.)*dinv ----
    k_gather<20><<<cdiv((long)NN * 20, 256), 256>>>(p_h, p_S, p_rowptr, p_csr);
    {
        dim3 grd(cdiv(156, 64), cdiv(NN, 128));
        k_gemm_tc<<<grd, 256>>>(p_S, p_dinv, 80, W2, b2, p_dinv,
                                p_u, 156, NN, 78, 156, 156, 1);
    }
    // ---- GCN layer 3: gather(156ch) then GEMM 156->312, out h3 ----
    k_gather<39><<<cdiv((long)NN * 39, 256), 256>>>(p_u, p_S, p_rowptr, p_csr);
    {
        dim3 grd(cdiv(312, 64), cdiv(NN, 128));
        k_gemm_tc<<<grd, 256>>>(p_S, p_dinv, 156, W3, b3, nullptr,
                                p_h, 312, NN, 156, 312, 312, 1);
    }

    // graph max pool + graph MLP -> c[:,0:128]
    k_segmax<<<NB, 128>>>(p_h, p_g);
    {
        dim3 grd(cdiv(1024, 64), cdiv(NB, 128));
        k_gemm_tc<<<grd, 256>>>(p_g, nullptr, 312, Wg1, bg1, nullptr,
                                p_gh, 1024, NB, 312, 1024, 1024, 1);
    }
    {
        dim3 grd(cdiv(128, 64), cdiv(NB, 128));
        k_gemm_tc<<<grd, 256>>>(p_gh, nullptr, 1024, Wg2, bg2, nullptr,
                                p_c, 256, NB, 1024, 128, 128, 0);
    }

    // conv tower -> tf, then FC -> c[:,128:256]
    k_tr_k2<<<cdiv(64 * 32 * 8, 256), 256>>>(k2, p_k2t);
    k_tr_k3<<<cdiv(128 * 64 * 8, 256), 256>>>(k3, p_k3t);
    cudaFuncSetAttribute(k_conv, cudaFuncAttributeMaxDynamicSharedMemorySize, 12736 * 4);
    k_conv<<<NB, 256, 12736 * 4>>>(xo, k1, kb1, p_k2t, kb2, p_k3t, kb3, p_tf);
    {
        dim3 grd(cdiv(128, 64), cdiv(NB, 128));
        k_gemm_tc<<<grd, 256>>>(p_tf, nullptr, 2944, Wxt, bxt, nullptr,
                                p_c + 128, 256, NB, 2944, 128, 128, 0);
    }

    // head
    {
        dim3 grd(cdiv(1024, 64), cdiv(NB, 128));
        k_gemm_tc<<<grd, 256>>>(p_c, nullptr, 256, Wf1, bf1, nullptr,
                                p_c1, 1024, NB, 256, 1024, 1024, 1);
    }
    {
        dim3 grd(cdiv(128, 64), cdiv(NB, 128));
        k_gemm_tc<<<grd, 256>>>(p_c1, nullptr, 1024, Wf2, bf2, nullptr,
                                p_c2, 128, NB, 1024, 128, 128, 1);
    }
    k_out<<<cdiv(NB * 32, 256), 256>>>(p_c2, Wo, bo, out);
}

// round 4
// speedup vs baseline: 2.1592x; 1.2530x over previous
#include <cuda_runtime.h>
#include <cstdint>

#define NN 163840
#define NE 2621440
#define NB 4096
#define NPG 40          // nodes per graph
#define NBLK 160        // NN / 1024

typedef unsigned long long ull;

// ---------------- device scratch (static, no allocations) ----------------
__device__ float g_u[NN * 312];      // v buffers (ping)
__device__ float g_S[NN * 312];      // aggregation output
__device__ float g_h[NN * 312];      // v buffers (pong) / h3
__device__ float g_dinv[NN];
__device__ int   g_deg[NN];
__device__ int   g_rowptr[NN + 1];
__device__ int   g_pos[NN];
__device__ int   g_csr[NE];
__device__ int   g_bsum[NBLK];
__device__ float g_g[NB * 312];      // graph max-pool
__device__ float g_gh[NB * 1024];
__device__ float g_c[NB * 256];      // concat [g2 | t]
__device__ float g_c1[NB * 1024];
__device__ float g_c2[NB * 128];
__device__ float g_tf[NB * 2944];    // flattened conv features
__device__ float g_k2t[32 * 8 * 64];   // k2 transposed to [ic][tap][oc]
__device__ float g_k3t[64 * 8 * 128];  // k3 transposed to [ic][tap][oc]

// ---------------- f32x2 packed helpers ----------------
__device__ __forceinline__ ull pk2(float lo, float hi) {
    ull r;
    asm("mov.b64 %0, {%1, %2};" : "=l"(r) : "f"(lo), "f"(hi));
    return r;
}
__device__ __forceinline__ ull bc2(float v) {
    ull r;
    asm("mov.b64 %0, {%1, %1};" : "=l"(r) : "f"(v));
    return r;
}
__device__ __forceinline__ void fma2(ull& d, ull a, ull b) {
    asm("fma.rn.f32x2 %0, %1, %2, %0;" : "+l"(d) : "l"(a), "l"(b));
}
__device__ __forceinline__ float2 upk2(ull v) {
    float2 f;
    asm("mov.b64 {%0, %1}, %2;" : "=f"(f.x), "=f"(f.y) : "l"(v));
    return f;
}

// ---------------- small utility kernels ----------------
__global__ void k_zero_i(int* p, int n) {
    int i = blockIdx.x * blockDim.x + threadIdx.x;
    if (i < n) p[i] = 0;
}
__global__ void k_degree(const int* __restrict__ dst, int* __restrict__ deg) {
    int e = blockIdx.x * blockDim.x + threadIdx.x;
    if (e < NE) atomicAdd(&deg[dst[e]], 1);
}
__global__ void k_dinv(const int* __restrict__ deg, float* __restrict__ dinv) {
    int i = blockIdx.x * blockDim.x + threadIdx.x;
    if (i < NN) dinv[i] = rsqrtf((float)deg[i] + 1.0f);
}
// v1[i,f] = x[i,f]*dinv[i], pad cols [78,80) with 0
__global__ void k_scale_pad(const float* __restrict__ x, const float* __restrict__ dinv,
                            float* __restrict__ v) {
    int idx = blockIdx.x * blockDim.x + threadIdx.x;
    if (idx >= NN * 80) return;
    int i = idx / 80, f = idx - i * 80;
    v[idx] = (f < 78) ? x[i * 78 + f] * dinv[i] : 0.f;
}

// ---------------- CSR build ----------------
__global__ void k_scan_block(const int* __restrict__ deg, int* __restrict__ rowptr,
                             int* __restrict__ bsum) {
    __shared__ int sm[256];
    int b = blockIdx.x, t = threadIdx.x;
    int base = b * 1024 + t * 4;
    int d0 = deg[base], d1 = deg[base + 1], d2 = deg[base + 2], d3 = deg[base + 3];
    int s = d0 + d1 + d2 + d3;
    sm[t] = s;
    __syncthreads();
    for (int off = 1; off < 256; off <<= 1) {
        int v2 = (t >= off) ? sm[t - off] : 0;
        __syncthreads();
        sm[t] += v2;
        __syncthreads();
    }
    int excl = sm[t] - s;
    rowptr[base] = excl;
    rowptr[base + 1] = excl + d0;
    rowptr[base + 2] = excl + d0 + d1;
    rowptr[base + 3] = excl + d0 + d1 + d2;
    if (t == 255) bsum[b] = sm[255];
}
__global__ void k_scan_bsum(int* __restrict__ bsum) {
    __shared__ int sm[256];
    int t = threadIdx.x;
    int v = (t < NBLK) ? bsum[t] : 0;
    sm[t] = v;
    __syncthreads();
    for (int off = 1; off < 256; off <<= 1) {
        int v2 = (t >= off) ? sm[t - off] : 0;
        __syncthreads();
        sm[t] += v2;
        __syncthreads();
    }
    if (t < NBLK) bsum[t] = sm[t] - v;
}
__global__ void k_scan_add(int* __restrict__ rowptr, const int* __restrict__ bsum,
                           int* __restrict__ pos) {
    int i = blockIdx.x * blockDim.x + threadIdx.x;
    if (i < NN) {
        int r = rowptr[i] + bsum[i >> 10];
        rowptr[i] = r;
        pos[i] = r;
    }
    if (i == 0) rowptr[NN] = NE;
}
__global__ void k_fill(const int* __restrict__ src, const int* __restrict__ dst,
                       int* __restrict__ pos, int* __restrict__ csr) {
    int e = blockIdx.x * blockDim.x + threadIdx.x;
    if (e >= NE) return;
    int slot = atomicAdd(&pos[dst[e]], 1);
    csr[slot] = src[e];
}

// ---------------- CSR gather: S[n] = v[n] + sum_{s in adj(n)} v[s] ----------------
template <int CH>
__global__ void k_gather(const float* __restrict__ v, float* __restrict__ S,
                         const int* __restrict__ rowptr, const int* __restrict__ csr)
{
    long idx = (long)blockIdx.x * blockDim.x + threadIdx.x;
    if (idx >= (long)NN * CH) return;
    int n = (int)(idx / CH);
    int c = (int)(idx - (long)n * CH);
    const float4* vp = (const float4*)v;
    float4 acc = vp[(long)n * CH + c];
    int e = rowptr[n], end = rowptr[n + 1];
    for (; e < end; e++) {
        int s = csr[e];
        float4 w = __ldg(&vp[(long)s * CH + c]);
        acc.x += w.x; acc.y += w.y; acc.z += w.z; acc.w += w.w;
    }
    ((float4*)S)[(long)n * CH + c] = acc;
}

// ---------------- TF32 tensor-core GEMM ----------------
__device__ __forceinline__ uint32_t f2tf32(float f) {
    uint32_t u;
    asm("cvt.rna.tf32.f32 %0, %1;" : "=r"(u) : "f"(f));
    return u;
}
__global__ void __launch_bounds__(256, 2)
k_gemm_tc(const float* __restrict__ A1,
          const float* __restrict__ rowScale, int lda,
          const float* __restrict__ W, const float* __restrict__ bias,
          const float* __restrict__ outScale,
          float* __restrict__ C, int ldc,
          int M, int K, int N, int Npad, int doRelu)
{
    __shared__ uint32_t As[128][36];
    __shared__ uint32_t Bs[32][72];

    int tid = threadIdx.x;
    int lane = tid & 31;
    int warp = tid >> 5;
    int warpM = warp & 3;
    int warpN = warp >> 2;
    int gid = lane >> 2, tig = lane & 3;
    int rowBase = blockIdx.y * 128;
    int colBase = blockIdx.x * 64;

    float acc[2][4][4];
#pragma unroll
    for (int mt = 0; mt < 2; mt++)
#pragma unroll
        for (int nt = 0; nt < 4; nt++)
#pragma unroll
            for (int r = 0; r < 4; r++) acc[mt][nt][r] = 0.f;

    for (int kt = 0; kt < K; kt += 32) {
#pragma unroll
        for (int l = 0; l < 16; l++) {
            int idx = tid + l * 256;
            int ml = idx >> 5, kl = idx & 31;
            int m = rowBase + ml, k = kt + kl;
            float v = 0.f;
            if (m < M && k < K) {
                v = A1[(long)m * lda + k];
                if (rowScale) v *= rowScale[m];
            }
            As[ml][kl] = f2tf32(v);
        }
#pragma unroll
        for (int l = 0; l < 8; l++) {
            int idx = tid + l * 256;
            int kl = idx >> 6, nl = idx & 63;
            int k = kt + kl, n = colBase + nl;
            float v = 0.f;
            if (k < K && n < N) v = W[(long)k * N + n];
            Bs[kl][nl] = f2tf32(v);
        }
        __syncthreads();

#pragma unroll
        for (int ks = 0; ks < 4; ks++) {
            int k0 = ks * 8;
            uint32_t a[2][4];
#pragma unroll
            for (int mt = 0; mt < 2; mt++) {
                int rb = warpM * 32 + mt * 16;
                a[mt][0] = As[rb + gid][k0 + tig];
                a[mt][1] = As[rb + gid + 8][k0 + tig];
                a[mt][2] = As[rb + gid][k0 + tig + 4];
                a[mt][3] = As[rb + gid + 8][k0 + tig + 4];
            }
            uint32_t b[4][2];
#pragma unroll
            for (int nt = 0; nt < 4; nt++) {
                int nb = warpN * 32 + nt * 8 + gid;
                b[nt][0] = Bs[k0 + tig][nb];
                b[nt][1] = Bs[k0 + tig + 4][nb];
            }
#pragma unroll
            for (int mt = 0; mt < 2; mt++)
#pragma unroll
                for (int nt = 0; nt < 4; nt++) {
                    asm volatile(
                        "mma.sync.aligned.m16n8k8.row.col.f32.tf32.tf32.f32 "
                        "{%0,%1,%2,%3}, {%4,%5,%6,%7}, {%8,%9}, {%0,%1,%2,%3};"
                        : "+f"(acc[mt][nt][0]), "+f"(acc[mt][nt][1]),
                          "+f"(acc[mt][nt][2]), "+f"(acc[mt][nt][3])
                        : "r"(a[mt][0]), "r"(a[mt][1]), "r"(a[mt][2]), "r"(a[mt][3]),
                          "r"(b[nt][0]), "r"(b[nt][1]));
                }
        }
        __syncthreads();
    }

#pragma unroll
    for (int mt = 0; mt < 2; mt++) {
#pragma unroll
        for (int nt = 0; nt < 4; nt++) {
#pragma unroll
            for (int r = 0; r < 4; r++) {
                int m = rowBase + warpM * 32 + mt * 16 + gid + ((r >= 2) ? 8 : 0);
                int n = colBase + warpN * 32 + nt * 8 + 2 * tig + (r & 1);
                if (m >= M || n >= Npad) continue;
                float v = 0.f;
                if (n < N) {
                    v = acc[mt][nt][r];
                    if (bias) v += bias[n];
                    if (doRelu) v = fmaxf(v, 0.f);
                    if (outScale) v *= outScale[m];
                }
                C[(long)m * ldc + n] = v;
            }
        }
    }
}

// per-graph max pool over 40 contiguous nodes, F=312 stride 312
__global__ void k_segmax(const float* __restrict__ h, float* __restrict__ g)
{
    int b = blockIdx.x;
    const float* p = h + (long)b * NPG * 312;
    for (int f = threadIdx.x; f < 312; f += blockDim.x) {
        float m = -3.4e38f;
#pragma unroll 4
        for (int n = 0; n < NPG; n++) m = fmaxf(m, p[n * 312 + f]);
        g[b * 312 + f] = m;
    }
}

// ---------------- conv weight transposes ----------------
__global__ void k_tr_k2(const float* __restrict__ k2, float* __restrict__ k2t) {
    int idx = blockIdx.x * blockDim.x + threadIdx.x;
    if (idx >= 64 * 32 * 8) return;
    int oc = idx >> 8, r = idx & 255, ic = r >> 3, i = r & 7;
    k2t[(ic * 8 + i) * 64 + oc] = k2[idx];
}
__global__ void k_tr_k3(const float* __restrict__ k3, float* __restrict__ k3t) {
    int idx = blockIdx.x * blockDim.x + threadIdx.x;
    if (idx >= 128 * 64 * 8) return;
    int oc = idx >> 9, r = idx & 511, ic = r >> 3, i = r & 7;
    k3t[(ic * 8 + i) * 128 + oc] = k3[idx];
}

// ---------------- fused conv tower: one CTA per graph, f32x2 packed FMA ----------------
__global__ void __launch_bounds__(256, 2)
k_conv(const float* __restrict__ xo,
       const float* __restrict__ k1, const float* __restrict__ kb1,
       const float* __restrict__ k2t, const float* __restrict__ kb2,
       const float* __restrict__ k3t, const float* __restrict__ kb3,
       float* __restrict__ tf)
{
    extern __shared__ float sm[];
    const int S_T1 = 0, S_T2 = 7744, S_IN = 7744, S_K1 = 8480, S_KB1 = 8736, S_T3 = 0;
    int b = blockIdx.x;
    int tid = threadIdx.x;

    for (int i = tid; i < 735; i += 256) sm[S_IN + i] = xo[(long)b * 735 + i];
    if (tid < 256) sm[S_K1 + tid] = k1[tid];
    if (tid < 32)  sm[S_KB1 + tid] = kb1[tid];
    __syncthreads();

    // stage 1: conv(1->32,k8) + relu + pool3 -> t1[32][242]
    for (int o = tid; o < 32 * 242; o += 256) {
        int ch = o / 242;
        int p = o - ch * 242;
        int base = 3 * p;
        const float* w = &sm[S_K1 + ch * 8];
        float s0 = 0.f, s1 = 0.f, s2 = 0.f;
#pragma unroll
        for (int i = 0; i < 8; i++) {
            float wv = w[i];
            s0 = fmaf(sm[S_IN + base + i],     wv, s0);
            s1 = fmaf(sm[S_IN + base + 1 + i], wv, s1);
            s2 = fmaf(sm[S_IN + base + 2 + i], wv, s2);
        }
        float m = fmaxf(fmaxf(s0, s1), s2) + sm[S_KB1 + ch];
        sm[S_T1 + o] = fmaxf(m, 0.f);
    }
    __syncthreads();

    // stage 2: conv(32->64,k8)+relu+pool3 -> t2[64][78]
    // thread = (oc pair: oc0=tid&31, oc1=oc0+32) x (tile = tid>>5 of 8)
    {
        int oc0 = tid & 31;
        int oc1 = oc0 + 32;
        int tile = tid >> 5;
        float bb0 = kb2[oc0], bb1 = kb2[oc1];
        for (int p0 = tile * 3; p0 < 78; p0 += 24) {
            int q0 = 3 * p0;
            ull acc[9];
#pragma unroll
            for (int r = 0; r < 9; r++) acc[r] = 0ull;
            for (int ic = 0; ic < 32; ic++) {
                const float* wl = &k2t[ic * 8 * 64];
                ull w[8];
#pragma unroll
                for (int i = 0; i < 8; i++)
                    w[i] = pk2(wl[i * 64 + oc0], wl[i * 64 + oc1]);
                const float* t1r = &sm[S_T1 + ic * 242];
                ull ib[16];
#pragma unroll
                for (int i = 0; i < 16; i++) {
                    int q = q0 + i;
                    ib[i] = bc2(t1r[q < 242 ? q : 241]);
                }
#pragma unroll
                for (int i = 0; i < 8; i++)
#pragma unroll
                    for (int r = 0; r < 9; r++)
                        fma2(acc[r], ib[r + i], w[i]);
            }
#pragma unroll
            for (int pp = 0; pp < 3; pp++) {
                int p = p0 + pp;
                if (p < 78) {
                    float2 a0 = upk2(acc[3 * pp]);
                    float2 a1 = upk2(acc[3 * pp + 1]);
                    float2 a2 = upk2(acc[3 * pp + 2]);
                    float m0 = fmaxf(fmaxf(a0.x, a1.x), a2.x) + bb0;
                    float m1 = fmaxf(fmaxf(a0.y, a1.y), a2.y) + bb1;
                    sm[S_T2 + oc0 * 78 + p] = fmaxf(m0, 0.f);
                    sm[S_T2 + oc1 * 78 + p] = fmaxf(m1, 0.f);
                }
            }
        }
    }
    __syncthreads();

    // stage 3: conv(64->128,k8)+relu+pool3 -> t3[128][23]
    // thread = (oc pair: oc0=tid&63, oc1=oc0+64) x (tile = tid>>6 of 4)
    {
        int oc0 = tid & 63;
        int oc1 = oc0 + 64;
        int tile = tid >> 6;
        float bb0 = kb3[oc0], bb1 = kb3[oc1];
        for (int p0 = tile * 3; p0 < 23; p0 += 12) {
            int q0 = 3 * p0;
            ull acc[9];
#pragma unroll
            for (int r = 0; r < 9; r++) acc[r] = 0ull;
            for (int ic = 0; ic < 64; ic++) {
                const float* wl = &k3t[ic * 8 * 128];
                ull w[8];
#pragma unroll
                for (int i = 0; i < 8; i++)
                    w[i] = pk2(wl[i * 128 + oc0], wl[i * 128 + oc1]);
                const float* t2r = &sm[S_T2 + ic * 78];
                ull ib[16];
#pragma unroll
                for (int i = 0; i < 16; i++) {
                    int q = q0 + i;
                    ib[i] = bc2(t2r[q < 78 ? q : 77]);
                }
#pragma unroll
                for (int i = 0; i < 8; i++)
#pragma unroll
                    for (int r = 0; r < 9; r++)
                        fma2(acc[r], ib[r + i], w[i]);
            }
#pragma unroll
            for (int pp = 0; pp < 3; pp++) {
                int p = p0 + pp;
                if (p < 23) {
                    float2 a0 = upk2(acc[3 * pp]);
                    float2 a1 = upk2(acc[3 * pp + 1]);
                    float2 a2 = upk2(acc[3 * pp + 2]);
                    float m0 = fmaxf(fmaxf(a0.x, a1.x), a2.x) + bb0;
                    float m1 = fmaxf(fmaxf(a0.y, a1.y), a2.y) + bb1;
                    sm[S_T3 + oc0 * 23 + p] = fmaxf(m0, 0.f);
                    sm[S_T3 + oc1 * 23 + p] = fmaxf(m1, 0.f);
                }
            }
        }
    }
    __syncthreads();

    for (int i = tid; i < 2944; i += 256) tf[(long)b * 2944 + i] = sm[S_T3 + i];
}

// final dot: out[b] = c2[b,:] . Wo + bo
__global__ void k_out(const float* __restrict__ c2, const float* __restrict__ Wo,
                      const float* __restrict__ bo, float* __restrict__ out)
{
    int warp = (blockIdx.x * blockDim.x + threadIdx.x) >> 5;
    int lane = threadIdx.x & 31;
    if (warp >= NB) return;
    float s = 0.f;
#pragma unroll
    for (int i = lane; i < 128; i += 32) s = fmaf(c2[warp * 128 + i], Wo[i], s);
#pragma unroll
    for (int off = 16; off; off >>= 1) s += __shfl_down_sync(0xffffffffu, s, off);
    if (lane == 0) out[warp] = s + bo[0];
}

// ---------------- launch ----------------
static inline int cdiv(long a, long b) { return (int)((a + b - 1) / b); }

extern "C" void kernel_launch(void* const* d_in, const int* in_sizes, int n_in,
                              void* d_out, int out_size)
{
    const float* x    = (const float*)d_in[0];
    const int*   ei   = (const int*)d_in[1];
    const float* xo   = (const float*)d_in[3];
    const float* W1   = (const float*)d_in[4];  const float* b1  = (const float*)d_in[5];
    const float* W2   = (const float*)d_in[6];  const float* b2  = (const float*)d_in[7];
    const float* W3   = (const float*)d_in[8];  const float* b3  = (const float*)d_in[9];
    const float* Wg1  = (const float*)d_in[10]; const float* bg1 = (const float*)d_in[11];
    const float* Wg2  = (const float*)d_in[12]; const float* bg2 = (const float*)d_in[13];
    const float* k1   = (const float*)d_in[14]; const float* kb1 = (const float*)d_in[15];
    const float* k2   = (const float*)d_in[16]; const float* kb2 = (const float*)d_in[17];
    const float* k3   = (const float*)d_in[18]; const float* kb3 = (const float*)d_in[19];
    const float* Wxt  = (const float*)d_in[20]; const float* bxt = (const float*)d_in[21];
    const float* Wf1  = (const float*)d_in[22]; const float* bf1 = (const float*)d_in[23];
    const float* Wf2  = (const float*)d_in[24]; const float* bf2 = (const float*)d_in[25];
    const float* Wo   = (const float*)d_in[26]; const float* bo  = (const float*)d_in[27];
    const int* src = ei;
    const int* dst = ei + NE;
    float* out = (float*)d_out;

    float *p_u, *p_S, *p_h, *p_dinv, *p_g, *p_gh, *p_c, *p_c1, *p_c2, *p_tf, *p_k2t, *p_k3t;
    int *p_deg, *p_rowptr, *p_pos, *p_csr, *p_bsum;
    cudaGetSymbolAddress((void**)&p_u, g_u);
    cudaGetSymbolAddress((void**)&p_S, g_S);
    cudaGetSymbolAddress((void**)&p_h, g_h);
    cudaGetSymbolAddress((void**)&p_dinv, g_dinv);
    cudaGetSymbolAddress((void**)&p_deg, g_deg);
    cudaGetSymbolAddress((void**)&p_rowptr, g_rowptr);
    cudaGetSymbolAddress((void**)&p_pos, g_pos);
    cudaGetSymbolAddress((void**)&p_csr, g_csr);
    cudaGetSymbolAddress((void**)&p_bsum, g_bsum);
    cudaGetSymbolAddress((void**)&p_g, g_g);
    cudaGetSymbolAddress((void**)&p_gh, g_gh);
    cudaGetSymbolAddress((void**)&p_c, g_c);
    cudaGetSymbolAddress((void**)&p_c1, g_c1);
    cudaGetSymbolAddress((void**)&p_c2, g_c2);
    cudaGetSymbolAddress((void**)&p_tf, g_tf);
    cudaGetSymbolAddress((void**)&p_k2t, g_k2t);
    cudaGetSymbolAddress((void**)&p_k3t, g_k3t);

    // degrees -> dinv ; CSR build
    k_zero_i<<<cdiv(NN, 256), 256>>>(p_deg, NN);
    k_degree<<<cdiv(NE, 256), 256>>>(dst, p_deg);
    k_dinv<<<cdiv(NN, 256), 256>>>(p_deg, p_dinv);
    k_scan_block<<<NBLK, 256>>>(p_deg, p_rowptr, p_bsum);
    k_scan_bsum<<<1, 256>>>(p_bsum);
    k_scan_add<<<cdiv(NN, 256), 256>>>(p_rowptr, p_bsum, p_pos);
    k_fill<<<cdiv(NE, 256), 256>>>(src, dst, p_pos, p_csr);

    // v1 = x * dinv (padded to 80 cols)
    k_scale_pad<<<cdiv((long)NN * 80, 256), 256>>>(x, p_dinv, p_u);

    // ---- GCN layer 1 ----
    k_gather<20><<<cdiv((long)NN * 20, 256), 256>>>(p_u, p_S, p_rowptr, p_csr);
    {
        dim3 grd(cdiv(80, 64), cdiv(NN, 128));
        k_gemm_tc<<<grd, 256>>>(p_S, p_dinv, 80, W1, b1, p_dinv,
                                p_h, 80, NN, 78, 78, 80, 1);
    }
    // ---- GCN layer 2 ----
    k_gather<20><<<cdiv((long)NN * 20, 256), 256>>>(p_h, p_S, p_rowptr, p_csr);
    {
        dim3 grd(cdiv(156, 64), cdiv(NN, 128));
        k_gemm_tc<<<grd, 256>>>(p_S, p_dinv, 80, W2, b2, p_dinv,
                                p_u, 156, NN, 78, 156, 156, 1);
    }
    // ---- GCN layer 3 ----
    k_gather<39><<<cdiv((long)NN * 39, 256), 256>>>(p_u, p_S, p_rowptr, p_csr);
    {
        dim3 grd(cdiv(312, 64), cdiv(NN, 128));
        k_gemm_tc<<<grd, 256>>>(p_S, p_dinv, 156, W3, b3, nullptr,
                                p_h, 312, NN, 156, 312, 312, 1);
    }

    // graph max pool + graph MLP -> c[:,0:128]
    k_segmax<<<NB, 128>>>(p_h, p_g);
    {
        dim3 grd(cdiv(1024, 64), cdiv(NB, 128));
        k_gemm_tc<<<grd, 256>>>(p_g, nullptr, 312, Wg1, bg1, nullptr,
                                p_gh, 1024, NB, 312, 1024, 1024, 1);
    }
    {
        dim3 grd(cdiv(128, 64), cdiv(NB, 128));
        k_gemm_tc<<<grd, 256>>>(p_gh, nullptr, 1024, Wg2, bg2, nullptr,
                                p_c, 256, NB, 1024, 128, 128, 0);
    }

    // conv tower -> tf, then FC -> c[:,128:256]
    k_tr_k2<<<cdiv(64 * 32 * 8, 256), 256>>>(k2, p_k2t);
    k_tr_k3<<<cdiv(128 * 64 * 8, 256), 256>>>(k3, p_k3t);
    cudaFuncSetAttribute(k_conv, cudaFuncAttributeMaxDynamicSharedMemorySize, 12736 * 4);
    k_conv<<<NB, 256, 12736 * 4>>>(xo, k1, kb1, p_k2t, kb2, p_k3t, kb3, p_tf);
    {
        dim3 grd(cdiv(128, 64), cdiv(NB, 128));
        k_gemm_tc<<<grd, 256>>>(p_tf, nullptr, 2944, Wxt, bxt, nullptr,
                                p_c + 128, 256, NB, 2944, 128, 128, 0);
    }

    // head
    {
        dim3 grd(cdiv(1024, 64), cdiv(NB, 128));
        k_gemm_tc<<<grd, 256>>>(p_c, nullptr, 256, Wf1, bf1, nullptr,
                                p_c1, 1024, NB, 256, 1024, 1024, 1);
    }
    {
        dim3 grd(cdiv(128, 64), cdiv(NB, 128));
        k_gemm_tc<<<grd, 256>>>(p_c1, nullptr, 1024, Wf2, bf2, nullptr,
                                p_c2, 128, NB, 1024, 128, 128, 1);
    }
    k_out<<<cdiv(NB * 32, 256), 256>>>(p_c2, Wo, bo, out);
}

// round 10
// speedup vs baseline: 2.3588x; 1.0925x over previous
#include <cuda_runtime.h>
#include <cstdint>

#define NN 163840
#define NE 2621440
#define NB 4096
#define NPG 40          // nodes per graph
#define NBLK 160        // NN / 1024

typedef unsigned long long ull;

// ---------------- device scratch (static, no allocations) ----------------
__device__ float g_u[NN * 312];      // v buffers (ping)
__device__ float g_S[NN * 312];      // aggregation output
__device__ float g_h[NN * 312];      // v buffers (pong) / h3
__device__ float g_dinv[NN];
__device__ int   g_deg[NN];
__device__ int   g_rowptr[NN + 1];
__device__ int   g_pos[NN];
__device__ int   g_csr[NE];
__device__ int   g_bsum[NBLK];
__device__ float g_g[NB * 312];      // graph max-pool
__device__ float g_gh[NB * 1024];
__device__ float g_c[NB * 256];      // concat [g2 | t]
__device__ float g_c1[NB * 1024];
__device__ float g_c2[NB * 128];
__device__ float g_tf[NB * 2944];    // flattened conv features
__device__ float g_k2t[32 * 8 * 64];   // k2 transposed to [ic][tap][oc]
__device__ float g_k3t[64 * 8 * 128];  // k3 transposed to [ic][tap][oc]

// ---------------- f32x2 packed helpers ----------------
__device__ __forceinline__ ull pk2(float lo, float hi) {
    ull r;
    asm("mov.b64 %0, {%1, %2};" : "=l"(r) : "f"(lo), "f"(hi));
    return r;
}
__device__ __forceinline__ ull bc2(float v) {
    ull r;
    asm("mov.b64 %0, {%1, %1};" : "=l"(r) : "f"(v));
    return r;
}
__device__ __forceinline__ void fma2(ull& d, ull a, ull b) {
    asm("fma.rn.f32x2 %0, %1, %2, %0;" : "+l"(d) : "l"(a), "l"(b));
}
__device__ __forceinline__ float2 upk2(ull v) {
    float2 f;
    asm("mov.b64 {%0, %1}, %2;" : "=f"(f.x), "=f"(f.y) : "l"(v));
    return f;
}
__device__ __forceinline__ uint32_t f2tf32(float f) {
    uint32_t u;
    asm("cvt.rna.tf32.f32 %0, %1;" : "=r"(u) : "f"(f));
    return u;
}

// ---------------- small utility kernels ----------------
__global__ void k_zero_i(int* p, int n) {
    int i = blockIdx.x * blockDim.x + threadIdx.x;
    if (i < n) p[i] = 0;
}
__global__ void k_degree(const int* __restrict__ dst, int* __restrict__ deg) {
    int e = blockIdx.x * blockDim.x + threadIdx.x;
    if (e < NE) atomicAdd(&deg[dst[e]], 1);
}
__global__ void k_dinv(const int* __restrict__ deg, float* __restrict__ dinv) {
    int i = blockIdx.x * blockDim.x + threadIdx.x;
    if (i < NN) dinv[i] = rsqrtf((float)deg[i] + 1.0f);
}
// v1[i,f] = x[i,f]*dinv[i], pad cols [78,80) with 0
__global__ void k_scale_pad(const float* __restrict__ x, const float* __restrict__ dinv,
                            float* __restrict__ v) {
    int idx = blockIdx.x * blockDim.x + threadIdx.x;
    if (idx >= NN * 80) return;
    int i = idx / 80, f = idx - i * 80;
    v[idx] = (f < 78) ? x[i * 78 + f] * dinv[i] : 0.f;
}

// ---------------- CSR build ----------------
__global__ void k_scan_block(const int* __restrict__ deg, int* __restrict__ rowptr,
                             int* __restrict__ bsum) {
    __shared__ int sm[256];
    int b = blockIdx.x, t = threadIdx.x;
    int base = b * 1024 + t * 4;
    int d0 = deg[base], d1 = deg[base + 1], d2 = deg[base + 2], d3 = deg[base + 3];
    int s = d0 + d1 + d2 + d3;
    sm[t] = s;
    __syncthreads();
    for (int off = 1; off < 256; off <<= 1) {
        int v2 = (t >= off) ? sm[t - off] : 0;
        __syncthreads();
        sm[t] += v2;
        __syncthreads();
    }
    int excl = sm[t] - s;
    rowptr[base] = excl;
    rowptr[base + 1] = excl + d0;
    rowptr[base + 2] = excl + d0 + d1;
    rowptr[base + 3] = excl + d0 + d1 + d2;
    if (t == 255) bsum[b] = sm[255];
}
__global__ void k_scan_bsum(int* __restrict__ bsum) {
    __shared__ int sm[256];
    int t = threadIdx.x;
    int v = (t < NBLK) ? bsum[t] : 0;
    sm[t] = v;
    __syncthreads();
    for (int off = 1; off < 256; off <<= 1) {
        int v2 = (t >= off) ? sm[t - off] : 0;
        __syncthreads();
        sm[t] += v2;
        __syncthreads();
    }
    if (t < NBLK) bsum[t] = sm[t] - v;
}
__global__ void k_scan_add(int* __restrict__ rowptr, const int* __restrict__ bsum,
                           int* __restrict__ pos) {
    int i = blockIdx.x * blockDim.x + threadIdx.x;
    if (i < NN) {
        int r = rowptr[i] + bsum[i >> 10];
        rowptr[i] = r;
        pos[i] = r;
    }
    if (i == 0) rowptr[NN] = NE;
}
__global__ void k_fill(const int* __restrict__ src, const int* __restrict__ dst,
                       int* __restrict__ pos, int* __restrict__ csr) {
    int e = blockIdx.x * blockDim.x + threadIdx.x;
    if (e >= NE) return;
    int slot = atomicAdd(&pos[dst[e]], 1);
    csr[slot] = src[e];
}

// ---------------- CSR gather: S[n] = v[n] + sum_{s in adj(n)} v[s] ----------------
template <int CH>
__global__ void k_gather(const float* __restrict__ v, float* __restrict__ S,
                         const int* __restrict__ rowptr, const int* __restrict__ csr)
{
    long idx = (long)blockIdx.x * blockDim.x + threadIdx.x;
    if (idx >= (long)NN * CH) return;
    int n = (int)(idx / CH);
    int c = (int)(idx - (long)n * CH);
    const float4* vp = (const float4*)v;
    float4 acc = vp[(long)n * CH + c];
    int e = rowptr[n], end = rowptr[n + 1];
    for (; e < end; e++) {
        int s = csr[e];
        float4 w = __ldg(&vp[(long)s * CH + c]);
        acc.x += w.x; acc.y += w.y; acc.z += w.z; acc.w += w.w;
    }
    ((float4*)S)[(long)n * CH + c] = acc;
}

// ---------------- TF32 tensor-core GEMM (R4 numerics, register-prefetch pipeline) ----
// C[m,n] = relu?( rowScale[m]*A[m,:] @ W[:,n] + bias[n] ) * outScale[m]
// BM=128, BN=64, BK=32, 256 threads. cvt.rna at STS time (exactly R4's rounding).
__global__ void __launch_bounds__(256, 2)
k_gemm_tc(const float* __restrict__ A1,
          const float* __restrict__ rowScale, int lda,
          const float* __restrict__ W, const float* __restrict__ bias,
          const float* __restrict__ outScale,
          float* __restrict__ C, int ldc,
          int M, int K, int N, int Npad, int doRelu)
{
    __shared__ uint32_t As[128][36];   // [m][k] tf32 bits, pad 4
    __shared__ uint32_t Bs[32][72];    // [k][n] tf32 bits, pad 8

    int tid = threadIdx.x;
    int lane = tid & 31;
    int warp = tid >> 5;
    int warpM = warp & 3;
    int warpN = warp >> 2;
    int gid = lane >> 2, tig = lane & 3;
    int rowBase = blockIdx.y * 128;
    int colBase = blockIdx.x * 64;
    int nT = (K + 31) / 32;
    bool nv4 = (N & 3) == 0;

    float4 ar[4];   // A prefetch regs: thread covers (ml = slot>>3, kg = slot&7), 4 floats each
    float4 br[2];   // B prefetch regs: (kl = slot>>4, ng = slot&15)

    auto ldA = [&](int kt) {
#pragma unroll
        for (int l = 0; l < 4; l++) {
            int slot = tid + l * 256;
            int ml = slot >> 3, kg = slot & 7;
            int m = rowBase + ml, k = kt + kg * 4;
            float4 v = make_float4(0.f, 0.f, 0.f, 0.f);
            if (m < M) {
                const float* p = A1 + (long)m * lda + k;
                if (k + 4 <= K) {
                    v = *(const float4*)p;          // lda%4==0 for all call sites
                } else {
                    if (k     < K) v.x = p[0];
                    if (k + 1 < K) v.y = p[1];
                    if (k + 2 < K) v.z = p[2];
                    if (k + 3 < K) v.w = p[3];
                }
                if (rowScale) {
                    float rs = rowScale[m];
                    v.x *= rs; v.y *= rs; v.z *= rs; v.w *= rs;
                }
            }
            ar[l] = v;
        }
    };
    auto ldB = [&](int kt) {
#pragma unroll
        for (int l = 0; l < 2; l++) {
            int slot = tid + l * 256;
            int kl = slot >> 4, ng = slot & 15;
            int k = kt + kl, n = colBase + ng * 4;
            float4 v = make_float4(0.f, 0.f, 0.f, 0.f);
            if (k < K) {
                const float* p = W + (long)k * N + n;
                if (nv4 && n + 4 <= N) {
                    v = *(const float4*)p;
                } else {
                    if (n     < N) v.x = p[0];
                    if (n + 1 < N) v.y = p[1];
                    if (n + 2 < N) v.z = p[2];
                    if (n + 3 < N) v.w = p[3];
                }
            }
            br[l] = v;
        }
    };
    auto stAB = [&]() {
#pragma unroll
        for (int l = 0; l < 4; l++) {
            int slot = tid + l * 256;
            int ml = slot >> 3, kg = slot & 7;
            As[ml][kg * 4 + 0] = f2tf32(ar[l].x);
            As[ml][kg * 4 + 1] = f2tf32(ar[l].y);
            As[ml][kg * 4 + 2] = f2tf32(ar[l].z);
            As[ml][kg * 4 + 3] = f2tf32(ar[l].w);
        }
#pragma unroll
        for (int l = 0; l < 2; l++) {
            int slot = tid + l * 256;
            int kl = slot >> 4, ng = slot & 15;
            Bs[kl][ng * 4 + 0] = f2tf32(br[l].x);
            Bs[kl][ng * 4 + 1] = f2tf32(br[l].y);
            Bs[kl][ng * 4 + 2] = f2tf32(br[l].z);
            Bs[kl][ng * 4 + 3] = f2tf32(br[l].w);
        }
    };

    float acc[2][4][4];
#pragma unroll
    for (int mt = 0; mt < 2; mt++)
#pragma unroll
        for (int nt = 0; nt < 4; nt++)
#pragma unroll
            for (int r = 0; r < 4; r++) acc[mt][nt][r] = 0.f;

    ldA(0); ldB(0);

    for (int it = 0; it < nT; it++) {
        stAB();
        __syncthreads();
        // prefetch next K-tile while this tile's MMAs run
        if (it + 1 < nT) { ldA((it + 1) * 32); ldB((it + 1) * 32); }

#pragma unroll
        for (int ks = 0; ks < 4; ks++) {
            int k0 = ks * 8;
            uint32_t a[2][4];
#pragma unroll
            for (int mt = 0; mt < 2; mt++) {
                int rb = warpM * 32 + mt * 16;
                a[mt][0] = As[rb + gid][k0 + tig];
                a[mt][1] = As[rb + gid + 8][k0 + tig];
                a[mt][2] = As[rb + gid][k0 + tig + 4];
                a[mt][3] = As[rb + gid + 8][k0 + tig + 4];
            }
            uint32_t b[4][2];
#pragma unroll
            for (int nt = 0; nt < 4; nt++) {
                int nb = warpN * 32 + nt * 8 + gid;
                b[nt][0] = Bs[k0 + tig][nb];
                b[nt][1] = Bs[k0 + tig + 4][nb];
            }
#pragma unroll
            for (int mt = 0; mt < 2; mt++)
#pragma unroll
                for (int nt = 0; nt < 4; nt++) {
                    asm volatile(
                        "mma.sync.aligned.m16n8k8.row.col.f32.tf32.tf32.f32 "
                        "{%0,%1,%2,%3}, {%4,%5,%6,%7}, {%8,%9}, {%0,%1,%2,%3};"
                        : "+f"(acc[mt][nt][0]), "+f"(acc[mt][nt][1]),
                          "+f"(acc[mt][nt][2]), "+f"(acc[mt][nt][3])
                        : "r"(a[mt][0]), "r"(a[mt][1]), "r"(a[mt][2]), "r"(a[mt][3]),
                          "r"(b[nt][0]), "r"(b[nt][1]));
                }
        }
        __syncthreads();
    }

    // epilogue (R4 verbatim)
#pragma unroll
    for (int mt = 0; mt < 2; mt++) {
#pragma unroll
        for (int nt = 0; nt < 4; nt++) {
#pragma unroll
            for (int r = 0; r < 4; r++) {
                int m = rowBase + warpM * 32 + mt * 16 + gid + ((r >= 2) ? 8 : 0);
                int n = colBase + warpN * 32 + nt * 8 + 2 * tig + (r & 1);
                if (m >= M || n >= Npad) continue;
                float v = 0.f;
                if (n < N) {
                    v = acc[mt][nt][r];
                    if (bias) v += bias[n];
                    if (doRelu) v = fmaxf(v, 0.f);
                    if (outScale) v *= outScale[m];
                }
                C[(long)m * ldc + n] = v;
            }
        }
    }
}

// per-graph max pool over 40 contiguous nodes, F=312 stride 312
__global__ void k_segmax(const float* __restrict__ h, float* __restrict__ g)
{
    int b = blockIdx.x;
    const float* p = h + (long)b * NPG * 312;
    for (int f = threadIdx.x; f < 312; f += blockDim.x) {
        float m = -3.4e38f;
#pragma unroll 4
        for (int n = 0; n < NPG; n++) m = fmaxf(m, p[n * 312 + f]);
        g[b * 312 + f] = m;
    }
}

// ---------------- conv weight transposes ----------------
__global__ void k_tr_k2(const float* __restrict__ k2, float* __restrict__ k2t) {
    int idx = blockIdx.x * blockDim.x + threadIdx.x;
    if (idx >= 64 * 32 * 8) return;
    int oc = idx >> 8, r = idx & 255, ic = r >> 3, i = r & 7;
    k2t[(ic * 8 + i) * 64 + oc] = k2[idx];
}
__global__ void k_tr_k3(const float* __restrict__ k3, float* __restrict__ k3t) {
    int idx = blockIdx.x * blockDim.x + threadIdx.x;
    if (idx >= 128 * 64 * 8) return;
    int oc = idx >> 9, r = idx & 511, ic = r >> 3, i = r & 7;
    k3t[(ic * 8 + i) * 128 + oc] = k3[idx];
}

// ---------------- fused conv tower: one CTA per graph, f32x2 packed FMA ----------------
__global__ void __launch_bounds__(256, 2)
k_conv(const float* __restrict__ xo,
       const float* __restrict__ k1, const float* __restrict__ kb1,
       const float* __restrict__ k2t, const float* __restrict__ kb2,
       const float* __restrict__ k3t, const float* __restrict__ kb3,
       float* __restrict__ tf)
{
    extern __shared__ float sm[];
    const int S_T1 = 0, S_T2 = 7744, S_IN = 7744, S_K1 = 8480, S_KB1 = 8736, S_T3 = 0;
    int b = blockIdx.x;
    int tid = threadIdx.x;

    for (int i = tid; i < 735; i += 256) sm[S_IN + i] = xo[(long)b * 735 + i];
    if (tid < 256) sm[S_K1 + tid] = k1[tid];
    if (tid < 32)  sm[S_KB1 + tid] = kb1[tid];
    __syncthreads();

    // stage 1: conv(1->32,k8) + relu + pool3 -> t1[32][242]
    for (int o = tid; o < 32 * 242; o += 256) {
        int ch = o / 242;
        int p = o - ch * 242;
        int base = 3 * p;
        const float* w = &sm[S_K1 + ch * 8];
        float s0 = 0.f, s1 = 0.f, s2 = 0.f;
#pragma unroll
        for (int i = 0; i < 8; i++) {
            float wv = w[i];
            s0 = fmaf(sm[S_IN + base + i],     wv, s0);
            s1 = fmaf(sm[S_IN + base + 1 + i], wv, s1);
            s2 = fmaf(sm[S_IN + base + 2 + i], wv, s2);
        }
        float m = fmaxf(fmaxf(s0, s1), s2) + sm[S_KB1 + ch];
        sm[S_T1 + o] = fmaxf(m, 0.f);
    }
    __syncthreads();

    // stage 2: conv(32->64,k8)+relu+pool3 -> t2[64][78]
    {
        int oc0 = tid & 31;
        int oc1 = oc0 + 32;
        int tile = tid >> 5;
        float bb0 = kb2[oc0], bb1 = kb2[oc1];
        for (int p0 = tile * 3; p0 < 78; p0 += 24) {
            int q0 = 3 * p0;
            ull acc[9];
#pragma unroll
            for (int r = 0; r < 9; r++) acc[r] = 0ull;
            for (int ic = 0; ic < 32; ic++) {
                const float* wl = &k2t[ic * 8 * 64];
                ull w[8];
#pragma unroll
                for (int i = 0; i < 8; i++)
                    w[i] = pk2(wl[i * 64 + oc0], wl[i * 64 + oc1]);
                const float* t1r = &sm[S_T1 + ic * 242];
                ull ib[16];
#pragma unroll
                for (int i = 0; i < 16; i++) {
                    int q = q0 + i;
                    ib[i] = bc2(t1r[q < 242 ? q : 241]);
                }
#pragma unroll
                for (int i = 0; i < 8; i++)
#pragma unroll
                    for (int r = 0; r < 9; r++)
                        fma2(acc[r], ib[r + i], w[i]);
            }
#pragma unroll
            for (int pp = 0; pp < 3; pp++) {
                int p = p0 + pp;
                if (p < 78) {
                    float2 a0 = upk2(acc[3 * pp]);
                    float2 a1 = upk2(acc[3 * pp + 1]);
                    float2 a2 = upk2(acc[3 * pp + 2]);
                    float m0 = fmaxf(fmaxf(a0.x, a1.x), a2.x) + bb0;
                    float m1 = fmaxf(fmaxf(a0.y, a1.y), a2.y) + bb1;
                    sm[S_T2 + oc0 * 78 + p] = fmaxf(m0, 0.f);
                    sm[S_T2 + oc1 * 78 + p] = fmaxf(m1, 0.f);
                }
            }
        }
    }
    __syncthreads();

    // stage 3: conv(64->128,k8)+relu+pool3 -> t3[128][23]
    {
        int oc0 = tid & 63;
        int oc1 = oc0 + 64;
        int tile = tid >> 6;
        float bb0 = kb3[oc0], bb1 = kb3[oc1];
        for (int p0 = tile * 3; p0 < 23; p0 += 12) {
            int q0 = 3 * p0;
            ull acc[9];
#pragma unroll
            for (int r = 0; r < 9; r++) acc[r] = 0ull;
            for (int ic = 0; ic < 64; ic++) {
                const float* wl = &k3t[ic * 8 * 128];
                ull w[8];
#pragma unroll
                for (int i = 0; i < 8; i++)
                    w[i] = pk2(wl[i * 128 + oc0], wl[i * 128 + oc1]);
                const float* t2r = &sm[S_T2 + ic * 78];
                ull ib[16];
#pragma unroll
                for (int i = 0; i < 16; i++) {
                    int q = q0 + i;
                    ib[i] = bc2(t2r[q < 78 ? q : 77]);
                }
#pragma unroll
                for (int i = 0; i < 8; i++)
#pragma unroll
                    for (int r = 0; r < 9; r++)
                        fma2(acc[r], ib[r + i], w[i]);
            }
#pragma unroll
            for (int pp = 0; pp < 3; pp++) {
                int p = p0 + pp;
                if (p < 23) {
                    float2 a0 = upk2(acc[3 * pp]);
                    float2 a1 = upk2(acc[3 * pp + 1]);
                    float2 a2 = upk2(acc[3 * pp + 2]);
                    float m0 = fmaxf(fmaxf(a0.x, a1.x), a2.x) + bb0;
                    float m1 = fmaxf(fmaxf(a0.y, a1.y), a2.y) + bb1;
                    sm[S_T3 + oc0 * 23 + p] = fmaxf(m0, 0.f);
                    sm[S_T3 + oc1 * 23 + p] = fmaxf(m1, 0.f);
                }
            }
        }
    }
    __syncthreads();

    for (int i = tid; i < 2944; i += 256) tf[(long)b * 2944 + i] = sm[S_T3 + i];
}

// final dot: out[b] = c2[b,:] . Wo + bo
__global__ void k_out(const float* __restrict__ c2, const float* __restrict__ Wo,
                      const float* __restrict__ bo, float* __restrict__ out)
{
    int warp = (blockIdx.x * blockDim.x + threadIdx.x) >> 5;
    int lane = threadIdx.x & 31;
    if (warp >= NB) return;
    float s = 0.f;
#pragma unroll
    for (int i = lane; i < 128; i += 32) s = fmaf(c2[warp * 128 + i], Wo[i], s);
#pragma unroll
    for (int off = 16; off; off >>= 1) s += __shfl_down_sync(0xffffffffu, s, off);
    if (lane == 0) out[warp] = s + bo[0];
}

// ---------------- launch ----------------
static inline int cdiv(long a, long b) { return (int)((a + b - 1) / b); }

extern "C" void kernel_launch(void* const* d_in, const int* in_sizes, int n_in,
                              void* d_out, int out_size)
{
    const float* x    = (const float*)d_in[0];
    const int*   ei   = (const int*)d_in[1];
    const float* xo   = (const float*)d_in[3];
    const float* W1   = (const float*)d_in[4];  const float* b1  = (const float*)d_in[5];
    const float* W2   = (const float*)d_in[6];  const float* b2  = (const float*)d_in[7];
    const float* W3   = (const float*)d_in[8];  const float* b3  = (const float*)d_in[9];
    const float* Wg1  = (const float*)d_in[10]; const float* bg1 = (const float*)d_in[11];
    const float* Wg2  = (const float*)d_in[12]; const float* bg2 = (const float*)d_in[13];
    const float* k1   = (const float*)d_in[14]; const float* kb1 = (const float*)d_in[15];
    const float* k2   = (const float*)d_in[16]; const float* kb2 = (const float*)d_in[17];
    const float* k3   = (const float*)d_in[18]; const float* kb3 = (const float*)d_in[19];
    const float* Wxt  = (const float*)d_in[20]; const float* bxt = (const float*)d_in[21];
    const float* Wf1  = (const float*)d_in[22]; const float* bf1 = (const float*)d_in[23];
    const float* Wf2  = (const float*)d_in[24]; const float* bf2 = (const float*)d_in[25];
    const float* Wo   = (const float*)d_in[26]; const float* bo  = (const float*)d_in[27];
    const int* src = ei;
    const int* dst = ei + NE;
    float* out = (float*)d_out;

    float *p_u, *p_S, *p_h, *p_dinv, *p_g, *p_gh, *p_c, *p_c1, *p_c2, *p_tf, *p_k2t, *p_k3t;
    int *p_deg, *p_rowptr, *p_pos, *p_csr, *p_bsum;
    cudaGetSymbolAddress((void**)&p_u, g_u);
    cudaGetSymbolAddress((void**)&p_S, g_S);
    cudaGetSymbolAddress((void**)&p_h, g_h);
    cudaGetSymbolAddress((void**)&p_dinv, g_dinv);
    cudaGetSymbolAddress((void**)&p_deg, g_deg);
    cudaGetSymbolAddress((void**)&p_rowptr, g_rowptr);
    cudaGetSymbolAddress((void**)&p_pos, g_pos);
    cudaGetSymbolAddress((void**)&p_csr, g_csr);
    cudaGetSymbolAddress((void**)&p_bsum, g_bsum);
    cudaGetSymbolAddress((void**)&p_g, g_g);
    cudaGetSymbolAddress((void**)&p_gh, g_gh);
    cudaGetSymbolAddress((void**)&p_c, g_c);
    cudaGetSymbolAddress((void**)&p_c1, g_c1);
    cudaGetSymbolAddress((void**)&p_c2, g_c2);
    cudaGetSymbolAddress((void**)&p_tf, g_tf);
    cudaGetSymbolAddress((void**)&p_k2t, g_k2t);
    cudaGetSymbolAddress((void**)&p_k3t, g_k3t);

    cudaFuncSetAttribute(k_conv, cudaFuncAttributeMaxDynamicSharedMemorySize, 12736 * 4);

    // degrees -> dinv ; CSR build
    k_zero_i<<<cdiv(NN, 256), 256>>>(p_deg, NN);
    k_degree<<<cdiv(NE, 256), 256>>>(dst, p_deg);
    k_dinv<<<cdiv(NN, 256), 256>>>(p_deg, p_dinv);
    k_scan_block<<<NBLK, 256>>>(p_deg, p_rowptr, p_bsum);
    k_scan_bsum<<<1, 256>>>(p_bsum);
    k_scan_add<<<cdiv(NN, 256), 256>>>(p_rowptr, p_bsum, p_pos);
    k_fill<<<cdiv(NE, 256), 256>>>(src, dst, p_pos, p_csr);

    // v1 = x * dinv (padded to 80 cols)
    k_scale_pad<<<cdiv((long)NN * 80, 256), 256>>>(x, p_dinv, p_u);

    // ---- GCN layer 1 ----
    k_gather<20><<<cdiv((long)NN * 20, 256), 256>>>(p_u, p_S, p_rowptr, p_csr);
    {
        dim3 grd(cdiv(80, 64), cdiv(NN, 128));
        k_gemm_tc<<<grd, 256>>>(p_S, p_dinv, 80, W1, b1, p_dinv,
                                p_h, 80, NN, 78, 78, 80, 1);
    }
    // ---- GCN layer 2 ----
    k_gather<20><<<cdiv((long)NN * 20, 256), 256>>>(p_h, p_S, p_rowptr, p_csr);
    {
        dim3 grd(cdiv(156, 64), cdiv(NN, 128));
        k_gemm_tc<<<grd, 256>>>(p_S, p_dinv, 80, W2, b2, p_dinv,
                                p_u, 156, NN, 78, 156, 156, 1);
    }
    // ---- GCN layer 3 ----
    k_gather<39><<<cdiv((long)NN * 39, 256), 256>>>(p_u, p_S, p_rowptr, p_csr);
    {
        dim3 grd(cdiv(312, 64), cdiv(NN, 128));
        k_gemm_tc<<<grd, 256>>>(p_S, p_dinv, 156, W3, b3, nullptr,
                                p_h, 312, NN, 156, 312, 312, 1);
    }

    // graph max pool + graph MLP -> c[:,0:128]
    k_segmax<<<NB, 128>>>(p_h, p_g);
    {
        dim3 grd(cdiv(1024, 64), cdiv(NB, 128));
        k_gemm_tc<<<grd, 256>>>(p_g, nullptr, 312, Wg1, bg1, nullptr,
                                p_gh, 1024, NB, 312, 1024, 1024, 1);
    }
    {
        dim3 grd(cdiv(128, 64), cdiv(NB, 128));
        k_gemm_tc<<<grd, 256>>>(p_gh, nullptr, 1024, Wg2, bg2, nullptr,
                                p_c, 256, NB, 1024, 128, 128, 0);
    }

    // conv tower -> tf, then FC -> c[:,128:256]
    k_tr_k2<<<cdiv(64 * 32 * 8, 256), 256>>>(k2, p_k2t);
    k_tr_k3<<<cdiv(128 * 64 * 8, 256), 256>>>(k3, p_k3t);
    k_conv<<<NB, 256, 12736 * 4>>>(xo, k1, kb1, p_k2t, kb2, p_k3t, kb3, p_tf);
    {
        dim3 grd(cdiv(128, 64), cdiv(NB, 128));
        k_gemm_tc<<<grd, 256>>>(p_tf, nullptr, 2944, Wxt, bxt, nullptr,
                                p_c + 128, 256, NB, 2944, 128, 128, 0);
    }

    // head
    {
        dim3 grd(cdiv(1024, 64), cdiv(NB, 128));
        k_gemm_tc<<<grd, 256>>>(p_c, nullptr, 256, Wf1, bf1, nullptr,
                                p_c1, 1024, NB, 256, 1024, 1024, 1);
    }
    {
        dim3 grd(cdiv(128, 64), cdiv(NB, 128));
        k_gemm_tc<<<grd, 256>>>(p_c1, nullptr, 1024, Wf2, bf2, nullptr,
                                p_c2, 128, NB, 1024, 128, 128, 1);
    }
    k_out<<<cdiv(NB * 32, 256), 256>>>(p_c2, Wo, bo, out);
}

// round 12
// speedup vs baseline: 2.5133x; 1.0655x over previous
#include <cuda_runtime.h>
#include <cstdint>

#define NN 163840
#define NE 2621440
#define NB 4096
#define NPG 40          // nodes per graph
#define NBLK 160        // NN / 1024

typedef unsigned long long ull;

// ---------------- device scratch (static, no allocations) ----------------
__device__ float g_u[NN * 312];      // v buffers (ping)
__device__ float g_S[NN * 312];      // aggregation output
__device__ float g_h[NN * 312];      // v buffers (pong) / h3
__device__ float g_dinv[NN];
__device__ int   g_deg[NN];
__device__ int   g_rowptr[NN + 1];
__device__ int   g_pos[NN];
__device__ int   g_csr[NE];
__device__ int   g_bsum[NBLK];
__device__ float g_g[NB * 312];      // graph max-pool
__device__ float g_gh[NB * 1024];
__device__ float g_c[NB * 256];      // concat [g2 | t]
__device__ float g_c1[NB * 1024];
__device__ float g_c2[NB * 128];
__device__ float g_tf[NB * 2944];    // flattened conv features
__device__ float g_k2t[32 * 8 * 64];   // k2 transposed to [ic][tap][oc]
__device__ float g_k3t[64 * 8 * 128];  // k3 transposed to [ic][tap][oc]

// ---------------- f32x2 packed helpers ----------------
__device__ __forceinline__ ull pk2(float lo, float hi) {
    ull r;
    asm("mov.b64 %0, {%1, %2};" : "=l"(r) : "f"(lo), "f"(hi));
    return r;
}
__device__ __forceinline__ ull bc2(float v) {
    ull r;
    asm("mov.b64 %0, {%1, %1};" : "=l"(r) : "f"(v));
    return r;
}
__device__ __forceinline__ void fma2(ull& d, ull a, ull b) {
    asm("fma.rn.f32x2 %0, %1, %2, %0;" : "+l"(d) : "l"(a), "l"(b));
}
__device__ __forceinline__ float2 upk2(ull v) {
    float2 f;
    asm("mov.b64 {%0, %1}, %2;" : "=f"(f.x), "=f"(f.y) : "l"(v));
    return f;
}
__device__ __forceinline__ uint32_t f2tf32(float f) {
    uint32_t u;
    asm("cvt.rna.tf32.f32 %0, %1;" : "=r"(u) : "f"(f));
    return u;
}

// ---------------- small utility kernels ----------------
__global__ void k_zero_i(int* p, int n) {
    int i = blockIdx.x * blockDim.x + threadIdx.x;
    if (i < n) p[i] = 0;
}
__global__ void k_degree(const int* __restrict__ dst, int* __restrict__ deg) {
    int e = blockIdx.x * blockDim.x + threadIdx.x;
    if (e < NE) atomicAdd(&deg[dst[e]], 1);
}
__global__ void k_dinv(const int* __restrict__ deg, float* __restrict__ dinv) {
    int i = blockIdx.x * blockDim.x + threadIdx.x;
    if (i < NN) dinv[i] = rsqrtf((float)deg[i] + 1.0f);
}
// v1[i,f] = x[i,f]*dinv[i], pad cols [78,80) with 0
__global__ void k_scale_pad(const float* __restrict__ x, const float* __restrict__ dinv,
                            float* __restrict__ v) {
    int idx = blockIdx.x * blockDim.x + threadIdx.x;
    if (idx >= NN * 80) return;
    int i = idx / 80, f = idx - i * 80;
    v[idx] = (f < 78) ? x[i * 78 + f] * dinv[i] : 0.f;
}

// ---------------- CSR build ----------------
__global__ void k_scan_block(const int* __restrict__ deg, int* __restrict__ rowptr,
                             int* __restrict__ bsum) {
    __shared__ int sm[256];
    int b = blockIdx.x, t = threadIdx.x;
    int base = b * 1024 + t * 4;
    int d0 = deg[base], d1 = deg[base + 1], d2 = deg[base + 2], d3 = deg[base + 3];
    int s = d0 + d1 + d2 + d3;
    sm[t] = s;
    __syncthreads();
    for (int off = 1; off < 256; off <<= 1) {
        int v2 = (t >= off) ? sm[t - off] : 0;
        __syncthreads();
        sm[t] += v2;
        __syncthreads();
    }
    int excl = sm[t] - s;
    rowptr[base] = excl;
    rowptr[base + 1] = excl + d0;
    rowptr[base + 2] = excl + d0 + d1;
    rowptr[base + 3] = excl + d0 + d1 + d2;
    if (t == 255) bsum[b] = sm[255];
}
__global__ void k_scan_bsum(int* __restrict__ bsum) {
    __shared__ int sm[256];
    int t = threadIdx.x;
    int v = (t < NBLK) ? bsum[t] : 0;
    sm[t] = v;
    __syncthreads();
    for (int off = 1; off < 256; off <<= 1) {
        int v2 = (t >= off) ? sm[t - off] : 0;
        __syncthreads();
        sm[t] += v2;
        __syncthreads();
    }
    if (t < NBLK) bsum[t] = sm[t] - v;
}
__global__ void k_scan_add(int* __restrict__ rowptr, const int* __restrict__ bsum,
                           int* __restrict__ pos) {
    int i = blockIdx.x * blockDim.x + threadIdx.x;
    if (i < NN) {
        int r = rowptr[i] + bsum[i >> 10];
        rowptr[i] = r;
        pos[i] = r;
    }
    if (i == 0) rowptr[NN] = NE;
}
__global__ void k_fill(const int* __restrict__ src, const int* __restrict__ dst,
                       int* __restrict__ pos, int* __restrict__ csr) {
    int e = blockIdx.x * blockDim.x + threadIdx.x;
    if (e >= NE) return;
    int slot = atomicAdd(&pos[dst[e]], 1);
    csr[slot] = src[e];
}

// ------- CSR gather: S[n] = dinv[n] * (v[n] + sum_{s in adj(n)} v[s]) -------
template <int CH>
__global__ void k_gather(const float* __restrict__ v, float* __restrict__ S,
                         const int* __restrict__ rowptr, const int* __restrict__ csr,
                         const float* __restrict__ dinv)
{
    long idx = (long)blockIdx.x * blockDim.x + threadIdx.x;
    if (idx >= (long)NN * CH) return;
    int n = (int)(idx / CH);
    int c = (int)(idx - (long)n * CH);
    const float4* vp = (const float4*)v;
    float4 acc = vp[(long)n * CH + c];
    int e = rowptr[n], end = rowptr[n + 1];
    for (; e + 4 <= end; e += 4) {
        int s0 = csr[e], s1 = csr[e + 1], s2 = csr[e + 2], s3 = csr[e + 3];
        float4 w0 = __ldg(&vp[(long)s0 * CH + c]);
        float4 w1 = __ldg(&vp[(long)s1 * CH + c]);
        float4 w2 = __ldg(&vp[(long)s2 * CH + c]);
        float4 w3 = __ldg(&vp[(long)s3 * CH + c]);
        acc.x += w0.x + w1.x + w2.x + w3.x;
        acc.y += w0.y + w1.y + w2.y + w3.y;
        acc.z += w0.z + w1.z + w2.z + w3.z;
        acc.w += w0.w + w1.w + w2.w + w3.w;
    }
    for (; e < end; e++) {
        int s = csr[e];
        float4 w = __ldg(&vp[(long)s * CH + c]);
        acc.x += w.x; acc.y += w.y; acc.z += w.z; acc.w += w.w;
    }
    float di = dinv[n];
    acc.x *= di; acc.y *= di; acc.z *= di; acc.w *= di;
    ((float4*)S)[(long)n * CH + c] = acc;
}

// ---------------- TF32 tensor-core GEMM (register-prefetch pipeline) ----
// C[m,n] = relu?( A[m,:] @ W[:,n] + bias[n] ) * outScale[m]
// BM=128, BN=64, BK=32, 256 threads. cvt.rna at STS time. M multiple of 128.
__global__ void __launch_bounds__(256, 2)
k_gemm_tc(const float* __restrict__ A1, int lda,
          const float* __restrict__ W, const float* __restrict__ bias,
          const float* __restrict__ outScale,
          float* __restrict__ C, int ldc,
          int M, int K, int N, int Npad, int doRelu)
{
    __shared__ uint32_t As[128][36];   // [m][k] tf32 bits, pad 4
    __shared__ uint32_t Bs[32][72];    // [k][n] tf32 bits, pad 8

    int tid = threadIdx.x;
    int lane = tid & 31;
    int warp = tid >> 5;
    int warpM = warp & 3;
    int warpN = warp >> 2;
    int gid = lane >> 2, tig = lane & 3;
    int rowBase = blockIdx.y * 128;
    int colBase = blockIdx.x * 64;
    int nT = (K + 31) / 32;
    bool nv4 = (N & 3) == 0;

    float4 ar[4];
    float4 br[2];

    auto ldA = [&](int kt) {
#pragma unroll
        for (int l = 0; l < 4; l++) {
            int slot = tid + l * 256;
            int ml = slot >> 3, kg = slot & 7;
            int m = rowBase + ml, k = kt + kg * 4;
            float4 v = make_float4(0.f, 0.f, 0.f, 0.f);
            if (m < M) {
                const float* p = A1 + (long)m * lda + k;
                if (k + 4 <= K) {
                    v = *(const float4*)p;
                } else {
                    if (k     < K) v.x = p[0];
                    if (k + 1 < K) v.y = p[1];
                    if (k + 2 < K) v.z = p[2];
                    if (k + 3 < K) v.w = p[3];
                }
            }
            ar[l] = v;
        }
    };
    auto ldB = [&](int kt) {
#pragma unroll
        for (int l = 0; l < 2; l++) {
            int slot = tid + l * 256;
            int kl = slot >> 4, ng = slot & 15;
            int k = kt + kl, n = colBase + ng * 4;
            float4 v = make_float4(0.f, 0.f, 0.f, 0.f);
            if (k < K) {
                const float* p = W + (long)k * N + n;
                if (nv4 && n + 4 <= N) {
                    v = *(const float4*)p;
                } else {
                    if (n     < N) v.x = p[0];
                    if (n + 1 < N) v.y = p[1];
                    if (n + 2 < N) v.z = p[2];
                    if (n + 3 < N) v.w = p[3];
                }
            }
            br[l] = v;
        }
    };
    auto stAB = [&]() {
#pragma unroll
        for (int l = 0; l < 4; l++) {
            int slot = tid + l * 256;
            int ml = slot >> 3, kg = slot & 7;
            As[ml][kg * 4 + 0] = f2tf32(ar[l].x);
            As[ml][kg * 4 + 1] = f2tf32(ar[l].y);
            As[ml][kg * 4 + 2] = f2tf32(ar[l].z);
            As[ml][kg * 4 + 3] = f2tf32(ar[l].w);
        }
#pragma unroll
        for (int l = 0; l < 2; l++) {
            int slot = tid + l * 256;
            int kl = slot >> 4, ng = slot & 15;
            Bs[kl][ng * 4 + 0] = f2tf32(br[l].x);
            Bs[kl][ng * 4 + 1] = f2tf32(br[l].y);
            Bs[kl][ng * 4 + 2] = f2tf32(br[l].z);
            Bs[kl][ng * 4 + 3] = f2tf32(br[l].w);
        }
    };

    float acc[2][4][4];
#pragma unroll
    for (int mt = 0; mt < 2; mt++)
#pragma unroll
        for (int nt = 0; nt < 4; nt++)
#pragma unroll
            for (int r = 0; r < 4; r++) acc[mt][nt][r] = 0.f;

    ldA(0); ldB(0);

    for (int it = 0; it < nT; it++) {
        stAB();
        __syncthreads();
        if (it + 1 < nT) { ldA((it + 1) * 32); ldB((it + 1) * 32); }

#pragma unroll
        for (int ks = 0; ks < 4; ks++) {
            int k0 = ks * 8;
            uint32_t a[2][4];
#pragma unroll
            for (int mt = 0; mt < 2; mt++) {
                int rb = warpM * 32 + mt * 16;
                a[mt][0] = As[rb + gid][k0 + tig];
                a[mt][1] = As[rb + gid + 8][k0 + tig];
                a[mt][2] = As[rb + gid][k0 + tig + 4];
                a[mt][3] = As[rb + gid + 8][k0 + tig + 4];
            }
            uint32_t b[4][2];
#pragma unroll
            for (int nt = 0; nt < 4; nt++) {
                int nb = warpN * 32 + nt * 8 + gid;
                b[nt][0] = Bs[k0 + tig][nb];
                b[nt][1] = Bs[k0 + tig + 4][nb];
            }
#pragma unroll
            for (int mt = 0; mt < 2; mt++)
#pragma unroll
                for (int nt = 0; nt < 4; nt++) {
                    asm volatile(
                        "mma.sync.aligned.m16n8k8.row.col.f32.tf32.tf32.f32 "
                        "{%0,%1,%2,%3}, {%4,%5,%6,%7}, {%8,%9}, {%0,%1,%2,%3};"
                        : "+f"(acc[mt][nt][0]), "+f"(acc[mt][nt][1]),
                          "+f"(acc[mt][nt][2]), "+f"(acc[mt][nt][3])
                        : "r"(a[mt][0]), "r"(a[mt][1]), "r"(a[mt][2]), "r"(a[mt][3]),
                          "r"(b[nt][0]), "r"(b[nt][1]));
                }
        }
        __syncthreads();
    }

#pragma unroll
    for (int mt = 0; mt < 2; mt++) {
#pragma unroll
        for (int nt = 0; nt < 4; nt++) {
#pragma unroll
            for (int r = 0; r < 4; r++) {
                int m = rowBase + warpM * 32 + mt * 16 + gid + ((r >= 2) ? 8 : 0);
                int n = colBase + warpN * 32 + nt * 8 + 2 * tig + (r & 1);
                if (m >= M || n >= Npad) continue;
                float v = 0.f;
                if (n < N) {
                    v = acc[mt][nt][r];
                    if (bias) v += bias[n];
                    if (doRelu) v = fmaxf(v, 0.f);
                    if (outScale) v *= outScale[m];
                }
                C[(long)m * ldc + n] = v;
            }
        }
    }
}

// per-graph max pool over 40 contiguous nodes, F=312 stride 312
__global__ void k_segmax(const float* __restrict__ h, float* __restrict__ g)
{
    int b = blockIdx.x;
    const float* p = h + (long)b * NPG * 312;
    for (int f = threadIdx.x; f < 312; f += blockDim.x) {
        float m = -3.4e38f;
#pragma unroll 4
        for (int n = 0; n < NPG; n++) m = fmaxf(m, p[n * 312 + f]);
        g[b * 312 + f] = m;
    }
}

// ---------------- conv weight transposes ----------------
__global__ void k_tr_k2(const float* __restrict__ k2, float* __restrict__ k2t) {
    int idx = blockIdx.x * blockDim.x + threadIdx.x;
    if (idx >= 64 * 32 * 8) return;
    int oc = idx >> 8, r = idx & 255, ic = r >> 3, i = r & 7;
    k2t[(ic * 8 + i) * 64 + oc] = k2[idx];
}
__global__ void k_tr_k3(const float* __restrict__ k3, float* __restrict__ k3t) {
    int idx = blockIdx.x * blockDim.x + threadIdx.x;
    if (idx >= 128 * 64 * 8) return;
    int oc = idx >> 9, r = idx & 511, ic = r >> 3, i = r & 7;
    k3t[(ic * 8 + i) * 128 + oc] = k3[idx];
}

// ---------------- fused conv tower: one CTA per graph, f32x2 packed FMA ----------------
__global__ void __launch_bounds__(256, 2)
k_conv(const float* __restrict__ xo,
       const float* __restrict__ k1, const float* __restrict__ kb1,
       const float* __restrict__ k2t, const float* __restrict__ kb2,
       const float* __restrict__ k3t, const float* __restrict__ kb3,
       float* __restrict__ tf)
{
    extern __shared__ float sm[];
    const int S_T1 = 0, S_T2 = 7744, S_IN = 7744, S_K1 = 8480, S_KB1 = 8736, S_T3 = 0;
    int b = blockIdx.x;
    int tid = threadIdx.x;

    for (int i = tid; i < 735; i += 256) sm[S_IN + i] = xo[(long)b * 735 + i];
    if (tid < 256) sm[S_K1 + tid] = k1[tid];
    if (tid < 32)  sm[S_KB1 + tid] = kb1[tid];
    __syncthreads();

    // stage 1: conv(1->32,k8) + relu + pool3 -> t1[32][242]
    for (int o = tid; o < 32 * 242; o += 256) {
        int ch = o / 242;
        int p = o - ch * 242;
        int base = 3 * p;
        const float* w = &sm[S_K1 + ch * 8];
        float s0 = 0.f, s1 = 0.f, s2 = 0.f;
#pragma unroll
        for (int i = 0; i < 8; i++) {
            float wv = w[i];
            s0 = fmaf(sm[S_IN + base + i],     wv, s0);
            s1 = fmaf(sm[S_IN + base + 1 + i], wv, s1);
            s2 = fmaf(sm[S_IN + base + 2 + i], wv, s2);
        }
        float m = fmaxf(fmaxf(s0, s1), s2) + sm[S_KB1 + ch];
        sm[S_T1 + o] = fmaxf(m, 0.f);
    }
    __syncthreads();

    // stage 2: conv(32->64,k8)+relu+pool3 -> t2[64][78]
    {
        int oc0 = tid & 31;
        int oc1 = oc0 + 32;
        int tile = tid >> 5;
        float bb0 = kb2[oc0], bb1 = kb2[oc1];
        for (int p0 = tile * 3; p0 < 78; p0 += 24) {
            int q0 = 3 * p0;
            ull acc[9];
#pragma unroll
            for (int r = 0; r < 9; r++) acc[r] = 0ull;
            for (int ic = 0; ic < 32; ic++) {
                const float* wl = &k2t[ic * 8 * 64];
                ull w[8];
#pragma unroll
                for (int i = 0; i < 8; i++)
                    w[i] = pk2(wl[i * 64 + oc0], wl[i * 64 + oc1]);
                const float* t1r = &sm[S_T1 + ic * 242];
                ull ib[16];
#pragma unroll
                for (int i = 0; i < 16; i++) {
                    int q = q0 + i;
                    ib[i] = bc2(t1r[q < 242 ? q : 241]);
                }
#pragma unroll
                for (int i = 0; i < 8; i++)
#pragma unroll
                    for (int r = 0; r < 9; r++)
                        fma2(acc[r], ib[r + i], w[i]);
            }
#pragma unroll
            for (int pp = 0; pp < 3; pp++) {
                int p = p0 + pp;
                if (p < 78) {
                    float2 a0 = upk2(acc[3 * pp]);
                    float2 a1 = upk2(acc[3 * pp + 1]);
                    float2 a2 = upk2(acc[3 * pp + 2]);
                    float m0 = fmaxf(fmaxf(a0.x, a1.x), a2.x) + bb0;
                    float m1 = fmaxf(fmaxf(a0.y, a1.y), a2.y) + bb1;
                    sm[S_T2 + oc0 * 78 + p] = fmaxf(m0, 0.f);
                    sm[S_T2 + oc1 * 78 + p] = fmaxf(m1, 0.f);
                }
            }
        }
    }
    __syncthreads();

    // stage 3: conv(64->128,k8)+relu+pool3 -> t3[128][23]
    {
        int oc0 = tid & 63;
        int oc1 = oc0 + 64;
        int tile = tid >> 6;
        float bb0 = kb3[oc0], bb1 = kb3[oc1];
        for (int p0 = tile * 3; p0 < 23; p0 += 12) {
            int q0 = 3 * p0;
            ull acc[9];
#pragma unroll
            for (int r = 0; r < 9; r++) acc[r] = 0ull;
            for (int ic = 0; ic < 64; ic++) {
                const float* wl = &k3t[ic * 8 * 128];
                ull w[8];
#pragma unroll
                for (int i = 0; i < 8; i++)
                    w[i] = pk2(wl[i * 128 + oc0], wl[i * 128 + oc1]);
                const float* t2r = &sm[S_T2 + ic * 78];
                ull ib[16];
#pragma unroll
                for (int i = 0; i < 16; i++) {
                    int q = q0 + i;
                    ib[i] = bc2(t2r[q < 78 ? q : 77]);
                }
#pragma unroll
                for (int i = 0; i < 8; i++)
#pragma unroll
                    for (int r = 0; r < 9; r++)
                        fma2(acc[r], ib[r + i], w[i]);
            }
#pragma unroll
            for (int pp = 0; pp < 3; pp++) {
                int p = p0 + pp;
                if (p < 23) {
                    float2 a0 = upk2(acc[3 * pp]);
                    float2 a1 = upk2(acc[3 * pp + 1]);
                    float2 a2 = upk2(acc[3 * pp + 2]);
                    float m0 = fmaxf(fmaxf(a0.x, a1.x), a2.x) + bb0;
                    float m1 = fmaxf(fmaxf(a0.y, a1.y), a2.y) + bb1;
                    sm[S_T3 + oc0 * 23 + p] = fmaxf(m0, 0.f);
                    sm[S_T3 + oc1 * 23 + p] = fmaxf(m1, 0.f);
                }
            }
        }
    }
    __syncthreads();

    for (int i = tid; i < 2944; i += 256) tf[(long)b * 2944 + i] = sm[S_T3 + i];
}

// final dot: out[b] = c2[b,:] . Wo + bo
__global__ void k_out(const float* __restrict__ c2, const float* __restrict__ Wo,
                      const float* __restrict__ bo, float* __restrict__ out)
{
    int warp = (blockIdx.x * blockDim.x + threadIdx.x) >> 5;
    int lane = threadIdx.x & 31;
    if (warp >= NB) return;
    float s = 0.f;
#pragma unroll
    for (int i = lane; i < 128; i += 32) s = fmaf(c2[warp * 128 + i], Wo[i], s);
#pragma unroll
    for (int off = 16; off; off >>= 1) s += __shfl_down_sync(0xffffffffu, s, off);
    if (lane == 0) out[warp] = s + bo[0];
}

// ---------------- launch ----------------
static inline int cdiv(long a, long b) { return (int)((a + b - 1) / b); }

extern "C" void kernel_launch(void* const* d_in, const int* in_sizes, int n_in,
                              void* d_out, int out_size)
{
    const float* x    = (const float*)d_in[0];
    const int*   ei   = (const int*)d_in[1];
    const float* xo   = (const float*)d_in[3];
    const float* W1   = (const float*)d_in[4];  const float* b1  = (const float*)d_in[5];
    const float* W2   = (const float*)d_in[6];  const float* b2  = (const float*)d_in[7];
    const float* W3   = (const float*)d_in[8];  const float* b3  = (const float*)d_in[9];
    const float* Wg1  = (const float*)d_in[10]; const float* bg1 = (const float*)d_in[11];
    const float* Wg2  = (const float*)d_in[12]; const float* bg2 = (const float*)d_in[13];
    const float* k1   = (const float*)d_in[14]; const float* kb1 = (const float*)d_in[15];
    const float* k2   = (const float*)d_in[16]; const float* kb2 = (const float*)d_in[17];
    const float* k3   = (const float*)d_in[18]; const float* kb3 = (const float*)d_in[19];
    const float* Wxt  = (const float*)d_in[20]; const float* bxt = (const float*)d_in[21];
    const float* Wf1  = (const float*)d_in[22]; const float* bf1 = (const float*)d_in[23];
    const float* Wf2  = (const float*)d_in[24]; const float* bf2 = (const float*)d_in[25];
    const float* Wo   = (const float*)d_in[26]; const float* bo  = (const float*)d_in[27];
    const int* src = ei;
    const int* dst = ei + NE;
    float* out = (float*)d_out;

    float *p_u, *p_S, *p_h, *p_dinv, *p_g, *p_gh, *p_c, *p_c1, *p_c2, *p_tf, *p_k2t, *p_k3t;
    int *p_deg, *p_rowptr, *p_pos, *p_csr, *p_bsum;
    cudaGetSymbolAddress((void**)&p_u, g_u);
    cudaGetSymbolAddress((void**)&p_S, g_S);
    cudaGetSymbolAddress((void**)&p_h, g_h);
    cudaGetSymbolAddress((void**)&p_dinv, g_dinv);
    cudaGetSymbolAddress((void**)&p_deg, g_deg);
    cudaGetSymbolAddress((void**)&p_rowptr, g_rowptr);
    cudaGetSymbolAddress((void**)&p_pos, g_pos);
    cudaGetSymbolAddress((void**)&p_csr, g_csr);
    cudaGetSymbolAddress((void**)&p_bsum, g_bsum);
    cudaGetSymbolAddress((void**)&p_g, g_g);
    cudaGetSymbolAddress((void**)&p_gh, g_gh);
    cudaGetSymbolAddress((void**)&p_c, g_c);
    cudaGetSymbolAddress((void**)&p_c1, g_c1);
    cudaGetSymbolAddress((void**)&p_c2, g_c2);
    cudaGetSymbolAddress((void**)&p_tf, g_tf);
    cudaGetSymbolAddress((void**)&p_k2t, g_k2t);
    cudaGetSymbolAddress((void**)&p_k3t, g_k3t);

    cudaFuncSetAttribute(k_conv, cudaFuncAttributeMaxDynamicSharedMemorySize, 12736 * 4);

    // degrees -> dinv ; CSR build
    k_zero_i<<<cdiv(NN, 256), 256>>>(p_deg, NN);
    k_degree<<<cdiv(NE, 256), 256>>>(dst, p_deg);
    k_dinv<<<cdiv(NN, 256), 256>>>(p_deg, p_dinv);
    k_scan_block<<<NBLK, 256>>>(p_deg, p_rowptr, p_bsum);
    k_scan_bsum<<<1, 256>>>(p_bsum);
    k_scan_add<<<cdiv(NN, 256), 256>>>(p_rowptr, p_bsum, p_pos);
    k_fill<<<cdiv(NE, 256), 256>>>(src, dst, p_pos, p_csr);

    // v1 = x * dinv (padded to 80 cols)
    k_scale_pad<<<cdiv((long)NN * 80, 256), 256>>>(x, p_dinv, p_u);

    // ---- GCN layer 1 ----
    k_gather<20><<<cdiv((long)NN * 20, 256), 256>>>(p_u, p_S, p_rowptr, p_csr, p_dinv);
    {
        dim3 grd(cdiv(80, 64), cdiv(NN, 128));
        k_gemm_tc<<<grd, 256>>>(p_S, 80, W1, b1, p_dinv,
                                p_h, 80, NN, 78, 78, 80, 1);
    }
    // ---- GCN layer 2 ----
    k_gather<20><<<cdiv((long)NN * 20, 256), 256>>>(p_h, p_S, p_rowptr, p_csr, p_dinv);
    {
        dim3 grd(cdiv(156, 64), cdiv(NN, 128));
        k_gemm_tc<<<grd, 256>>>(p_S, 80, W2, b2, p_dinv,
                                p_u, 156, NN, 78, 156, 156, 1);
    }
    // ---- GCN layer 3 ----
    k_gather<39><<<cdiv((long)NN * 39, 256), 256>>>(p_u, p_S, p_rowptr, p_csr, p_dinv);
    {
        dim3 grd(cdiv(312, 64), cdiv(NN, 128));
        k_gemm_tc<<<grd, 256>>>(p_S, 156, W3, b3, nullptr,
                                p_h, 312, NN, 156, 312, 312, 1);
    }

    // graph max pool + graph MLP -> c[:,0:128]
    k_segmax<<<NB, 128>>>(p_h, p_g);
    {
        dim3 grd(cdiv(1024, 64), cdiv(NB, 128));
        k_gemm_tc<<<grd, 256>>>(p_g, 312, Wg1, bg1, nullptr,
                                p_gh, 1024, NB, 312, 1024, 1024, 1);
    }
    {
        dim3 grd(cdiv(128, 64), cdiv(NB, 128));
        k_gemm_tc<<<grd, 256>>>(p_gh, 1024, Wg2, bg2, nullptr,
                                p_c, 256, NB, 1024, 128, 128, 0);
    }

    // conv tower -> tf, then FC -> c[:,128:256]
    k_tr_k2<<<cdiv(64 * 32 * 8, 256), 256>>>(k2, p_k2t);
    k_tr_k3<<<cdiv(128 * 64 * 8, 256), 256>>>(k3, p_k3t);
    k_conv<<<NB, 256, 12736 * 4>>>(xo, k1, kb1, p_k2t, kb2, p_k3t, kb3, p_tf);
    {
        dim3 grd(cdiv(128, 64), cdiv(NB, 128));
        k_gemm_tc<<<grd, 256>>>(p_tf, 2944, Wxt, bxt, nullptr,
                                p_c + 128, 256, NB, 2944, 128, 128, 0);
    }

    // head
    {
        dim3 grd(cdiv(1024, 64), cdiv(NB, 128));
        k_gemm_tc<<<grd, 256>>>(p_c, 256, Wf1, bf1, nullptr,
                                p_c1, 1024, NB, 256, 1024, 1024, 1);
    }
    {
        dim3 grd(cdiv(128, 64), cdiv(NB, 128));
        k_gemm_tc<<<grd, 256>>>(p_c1, 1024, Wf2, bf2, nullptr,
                                p_c2, 128, NB, 1024, 128, 128, 1);
    }
    k_out<<<cdiv(NB * 32, 256), 256>>>(p_c2, Wo, bo, out);
}

// round 17
// speedup vs baseline: 2.6613x; 1.0589x over previous
#include <cuda_runtime.h>
#include <cstdint>

#define NN 163840
#define NE 2621440
#define NB 4096
#define NPG 40          // nodes per graph
#define NBLK 160        // NN / 1024

typedef unsigned long long ull;

// ---------------- device scratch (static, no allocations) ----------------
__device__ float g_u[NN * 312];      // v buffers (ping)
__device__ float g_S[NN * 312];      // aggregation output
__device__ float g_h[NN * 312];      // v buffers (pong) / h3
__device__ float g_dinv[NN];
__device__ int   g_deg[NN];
__device__ int   g_rowptr[NN + 1];
__device__ int   g_pos[NN];
__device__ int   g_csr[NE];
__device__ int   g_bsum[NBLK];
__device__ float g_g[NB * 312];      // graph max-pool
__device__ float g_gh[NB * 1024];
__device__ float g_c[NB * 256];      // concat [g2 | t]
__device__ float g_c1[NB * 1024];
__device__ float g_c2[NB * 128];
__device__ float g_tf[NB * 2944];    // flattened conv features
__device__ float g_k2t[32 * 8 * 64];   // k2 transposed to [ic][tap][oc]
__device__ float g_k3t[64 * 8 * 128];  // k3 transposed to [ic][tap][oc]

// ---------------- f32x2 packed helpers ----------------
__device__ __forceinline__ ull pk2(float lo, float hi) {
    ull r;
    asm("mov.b64 %0, {%1, %2};" : "=l"(r) : "f"(lo), "f"(hi));
    return r;
}
__device__ __forceinline__ ull bc2(float v) {
    ull r;
    asm("mov.b64 %0, {%1, %1};" : "=l"(r) : "f"(v));
    return r;
}
__device__ __forceinline__ void fma2(ull& d, ull a, ull b) {
    asm("fma.rn.f32x2 %0, %1, %2, %0;" : "+l"(d) : "l"(a), "l"(b));
}
__device__ __forceinline__ float2 upk2(ull v) {
    float2 f;
    asm("mov.b64 {%0, %1}, %2;" : "=f"(f.x), "=f"(f.y) : "l"(v));
    return f;
}
__device__ __forceinline__ uint32_t f2tf32(float f) {
    uint32_t u;
    asm("cvt.rna.tf32.f32 %0, %1;" : "=r"(u) : "f"(f));
    return u;
}

// ---------------- small utility kernels ----------------
__global__ void k_zero_i(int* p, int n) {
    int i = blockIdx.x * blockDim.x + threadIdx.x;
    if (i < n) p[i] = 0;
}
__global__ void k_degree(const int* __restrict__ dst, int* __restrict__ deg) {
    int e = blockIdx.x * blockDim.x + threadIdx.x;
    if (e < NE) atomicAdd(&deg[dst[e]], 1);
}
__global__ void k_dinv(const int* __restrict__ deg, float* __restrict__ dinv) {
    int i = blockIdx.x * blockDim.x + threadIdx.x;
    if (i < NN) dinv[i] = rsqrtf((float)deg[i] + 1.0f);
}
// v1[i,f] = x[i,f]*dinv[i], pad cols [78,80) with 0
__global__ void k_scale_pad(const float* __restrict__ x, const float* __restrict__ dinv,
                            float* __restrict__ v) {
    int idx = blockIdx.x * blockDim.x + threadIdx.x;
    if (idx >= NN * 80) return;
    int i = idx / 80, f = idx - i * 80;
    v[idx] = (f < 78) ? x[i * 78 + f] * dinv[i] : 0.f;
}

// ---------------- CSR build ----------------
__global__ void k_scan_block(const int* __restrict__ deg, int* __restrict__ rowptr,
                             int* __restrict__ bsum) {
    __shared__ int sm[256];
    int b = blockIdx.x, t = threadIdx.x;
    int base = b * 1024 + t * 4;
    int d0 = deg[base], d1 = deg[base + 1], d2 = deg[base + 2], d3 = deg[base + 3];
    int s = d0 + d1 + d2 + d3;
    sm[t] = s;
    __syncthreads();
    for (int off = 1; off < 256; off <<= 1) {
        int v2 = (t >= off) ? sm[t - off] : 0;
        __syncthreads();
        sm[t] += v2;
        __syncthreads();
    }
    int excl = sm[t] - s;
    rowptr[base] = excl;
    rowptr[base + 1] = excl + d0;
    rowptr[base + 2] = excl + d0 + d1;
    rowptr[base + 3] = excl + d0 + d1 + d2;
    if (t == 255) bsum[b] = sm[255];
}
__global__ void k_scan_bsum(int* __restrict__ bsum) {
    __shared__ int sm[256];
    int t = threadIdx.x;
    int v = (t < NBLK) ? bsum[t] : 0;
    sm[t] = v;
    __syncthreads();
    for (int off = 1; off < 256; off <<= 1) {
        int v2 = (t >= off) ? sm[t - off] : 0;
        __syncthreads();
        sm[t] += v2;
        __syncthreads();
    }
    if (t < NBLK) bsum[t] = sm[t] - v;
}
__global__ void k_scan_add(int* __restrict__ rowptr, const int* __restrict__ bsum,
                           int* __restrict__ pos) {
    int i = blockIdx.x * blockDim.x + threadIdx.x;
    if (i < NN) {
        int r = rowptr[i] + bsum[i >> 10];
        rowptr[i] = r;
        pos[i] = r;
    }
    if (i == 0) rowptr[NN] = NE;
}
__global__ void k_fill(const int* __restrict__ src, const int* __restrict__ dst,
                       int* __restrict__ pos, int* __restrict__ csr) {
    int e = blockIdx.x * blockDim.x + threadIdx.x;
    if (e >= NE) return;
    int slot = atomicAdd(&pos[dst[e]], 1);
    csr[slot] = src[e];
}

// ------- CSR gather: S[n] = dinv[n] * (v[n] + sum_{s in adj(n)} v[s]) -------
template <int CH>
__global__ void k_gather(const float* __restrict__ v, float* __restrict__ S,
                         const int* __restrict__ rowptr, const int* __restrict__ csr,
                         const float* __restrict__ dinv)
{
    long idx = (long)blockIdx.x * blockDim.x + threadIdx.x;
    if (idx >= (long)NN * CH) return;
    int n = (int)(idx / CH);
    int c = (int)(idx - (long)n * CH);
    const float4* vp = (const float4*)v;
    float4 acc = vp[(long)n * CH + c];
    int e = rowptr[n], end = rowptr[n + 1];
    for (; e + 4 <= end; e += 4) {
        int s0 = csr[e], s1 = csr[e + 1], s2 = csr[e + 2], s3 = csr[e + 3];
        float4 w0 = __ldg(&vp[(long)s0 * CH + c]);
        float4 w1 = __ldg(&vp[(long)s1 * CH + c]);
        float4 w2 = __ldg(&vp[(long)s2 * CH + c]);
        float4 w3 = __ldg(&vp[(long)s3 * CH + c]);
        acc.x += w0.x + w1.x + w2.x + w3.x;
        acc.y += w0.y + w1.y + w2.y + w3.y;
        acc.z += w0.z + w1.z + w2.z + w3.z;
        acc.w += w0.w + w1.w + w2.w + w3.w;
    }
    for (; e < end; e++) {
        int s = csr[e];
        float4 w = __ldg(&vp[(long)s * CH + c]);
        acc.x += w.x; acc.y += w.y; acc.z += w.z; acc.w += w.w;
    }
    float di = dinv[n];
    acc.x *= di; acc.y *= di; acc.z *= di; acc.w *= di;
    ((float4*)S)[(long)n * CH + c] = acc;
}

// ---------------- TF32 tensor-core GEMM (register-prefetch pipeline) ----
// C[m,n] = relu?( A[m,:] @ W[:,n] + bias[n] ) * outScale[m]
__global__ void __launch_bounds__(256, 2)
k_gemm_tc(const float* __restrict__ A1, int lda,
          const float* __restrict__ W, const float* __restrict__ bias,
          const float* __restrict__ outScale,
          float* __restrict__ C, int ldc,
          int M, int K, int N, int Npad, int doRelu)
{
    __shared__ uint32_t As[128][36];   // [m][k] tf32 bits, pad 4
    __shared__ uint32_t Bs[32][72];    // [k][n] tf32 bits, pad 8

    int tid = threadIdx.x;
    int lane = tid & 31;
    int warp = tid >> 5;
    int warpM = warp & 3;
    int warpN = warp >> 2;
    int gid = lane >> 2, tig = lane & 3;
    int rowBase = blockIdx.y * 128;
    int colBase = blockIdx.x * 64;
    int nT = (K + 31) / 32;
    bool nv4 = (N & 3) == 0;

    float4 ar[4];
    float4 br[2];

    auto ldA = [&](int kt) {
#pragma unroll
        for (int l = 0; l < 4; l++) {
            int slot = tid + l * 256;
            int ml = slot >> 3, kg = slot & 7;
            int m = rowBase + ml, k = kt + kg * 4;
            float4 v = make_float4(0.f, 0.f, 0.f, 0.f);
            if (m < M) {
                const float* p = A1 + (long)m * lda + k;
                if (k + 4 <= K) {
                    v = *(const float4*)p;
                } else {
                    if (k     < K) v.x = p[0];
                    if (k + 1 < K) v.y = p[1];
                    if (k + 2 < K) v.z = p[2];
                    if (k + 3 < K) v.w = p[3];
                }
            }
            ar[l] = v;
        }
    };
    auto ldB = [&](int kt) {
#pragma unroll
        for (int l = 0; l < 2; l++) {
            int slot = tid + l * 256;
            int kl = slot >> 4, ng = slot & 15;
            int k = kt + kl, n = colBase + ng * 4;
            float4 v = make_float4(0.f, 0.f, 0.f, 0.f);
            if (k < K) {
                const float* p = W + (long)k * N + n;
                if (nv4 && n + 4 <= N) {
                    v = *(const float4*)p;
                } else {
                    if (n     < N) v.x = p[0];
                    if (n + 1 < N) v.y = p[1];
                    if (n + 2 < N) v.z = p[2];
                    if (n + 3 < N) v.w = p[3];
                }
            }
            br[l] = v;
        }
    };
    auto stAB = [&]() {
#pragma unroll
        for (int l = 0; l < 4; l++) {
            int slot = tid + l * 256;
            int ml = slot >> 3, kg = slot & 7;
            As[ml][kg * 4 + 0] = f2tf32(ar[l].x);
            As[ml][kg * 4 + 1] = f2tf32(ar[l].y);
            As[ml][kg * 4 + 2] = f2tf32(ar[l].z);
            As[ml][kg * 4 + 3] = f2tf32(ar[l].w);
        }
#pragma unroll
        for (int l = 0; l < 2; l++) {
            int slot = tid + l * 256;
            int kl = slot >> 4, ng = slot & 15;
            Bs[kl][ng * 4 + 0] = f2tf32(br[l].x);
            Bs[kl][ng * 4 + 1] = f2tf32(br[l].y);
            Bs[kl][ng * 4 + 2] = f2tf32(br[l].z);
            Bs[kl][ng * 4 + 3] = f2tf32(br[l].w);
        }
    };

    float acc[2][4][4];
#pragma unroll
    for (int mt = 0; mt < 2; mt++)
#pragma unroll
        for (int nt = 0; nt < 4; nt++)
#pragma unroll
            for (int r = 0; r < 4; r++) acc[mt][nt][r] = 0.f;

    ldA(0); ldB(0);

    for (int it = 0; it < nT; it++) {
        stAB();
        __syncthreads();
        if (it + 1 < nT) { ldA((it + 1) * 32); ldB((it + 1) * 32); }

#pragma unroll
        for (int ks = 0; ks < 4; ks++) {
            int k0 = ks * 8;
            uint32_t a[2][4];
#pragma unroll
            for (int mt = 0; mt < 2; mt++) {
                int rb = warpM * 32 + mt * 16;
                a[mt][0] = As[rb + gid][k0 + tig];
                a[mt][1] = As[rb + gid + 8][k0 + tig];
                a[mt][2] = As[rb + gid][k0 + tig + 4];
                a[mt][3] = As[rb + gid + 8][k0 + tig + 4];
            }
            uint32_t b[4][2];
#pragma unroll
            for (int nt = 0; nt < 4; nt++) {
                int nb = warpN * 32 + nt * 8 + gid;
                b[nt][0] = Bs[k0 + tig][nb];
                b[nt][1] = Bs[k0 + tig + 4][nb];
            }
#pragma unroll
            for (int mt = 0; mt < 2; mt++)
#pragma unroll
                for (int nt = 0; nt < 4; nt++) {
                    asm volatile(
                        "mma.sync.aligned.m16n8k8.row.col.f32.tf32.tf32.f32 "
                        "{%0,%1,%2,%3}, {%4,%5,%6,%7}, {%8,%9}, {%0,%1,%2,%3};"
                        : "+f"(acc[mt][nt][0]), "+f"(acc[mt][nt][1]),
                          "+f"(acc[mt][nt][2]), "+f"(acc[mt][nt][3])
                        : "r"(a[mt][0]), "r"(a[mt][1]), "r"(a[mt][2]), "r"(a[mt][3]),
                          "r"(b[nt][0]), "r"(b[nt][1]));
                }
        }
        __syncthreads();
    }

#pragma unroll
    for (int mt = 0; mt < 2; mt++) {
#pragma unroll
        for (int nt = 0; nt < 4; nt++) {
#pragma unroll
            for (int r = 0; r < 4; r++) {
                int m = rowBase + warpM * 32 + mt * 16 + gid + ((r >= 2) ? 8 : 0);
                int n = colBase + warpN * 32 + nt * 8 + 2 * tig + (r & 1);
                if (m >= M || n >= Npad) continue;
                float v = 0.f;
                if (n < N) {
                    v = acc[mt][nt][r];
                    if (bias) v += bias[n];
                    if (doRelu) v = fmaxf(v, 0.f);
                    if (outScale) v *= outScale[m];
                }
                C[(long)m * ldc + n] = v;
            }
        }
    }
}

// per-graph max pool over 40 contiguous nodes, F=312 stride 312
__global__ void k_segmax(const float* __restrict__ h, float* __restrict__ g)
{
    int b = blockIdx.x;
    const float* p = h + (long)b * NPG * 312;
    for (int f = threadIdx.x; f < 312; f += blockDim.x) {
        float m = -3.4e38f;
#pragma unroll 4
        for (int n = 0; n < NPG; n++) m = fmaxf(m, p[n * 312 + f]);
        g[b * 312 + f] = m;
    }
}

// ---------------- conv weight transposes ----------------
__global__ void k_tr_k2(const float* __restrict__ k2, float* __restrict__ k2t) {
    int idx = blockIdx.x * blockDim.x + threadIdx.x;
    if (idx >= 64 * 32 * 8) return;
    int oc = idx >> 8, r = idx & 255, ic = r >> 3, i = r & 7;
    k2t[(ic * 8 + i) * 64 + oc] = k2[idx];
}
__global__ void k_tr_k3(const float* __restrict__ k3, float* __restrict__ k3t) {
    int idx = blockIdx.x * blockDim.x + threadIdx.x;
    if (idx >= 128 * 64 * 8) return;
    int oc = idx >> 9, r = idx & 511, ic = r >> 3, i = r & 7;
    k3t[(ic * 8 + i) * 128 + oc] = k3[idx];
}

// ---------------- fused conv tower: one CTA per graph, f32x2 packed FMA ----------------
__global__ void __launch_bounds__(256, 2)
k_conv(const float* __restrict__ xo,
       const float* __restrict__ k1, const float* __restrict__ kb1,
       const float* __restrict__ k2t, const float* __restrict__ kb2,
       const float* __restrict__ k3t, const float* __restrict__ kb3,
       float* __restrict__ tf)
{
    extern __shared__ float sm[];
    const int S_T1 = 0, S_T2 = 7744, S_IN = 7744, S_K1 = 8480, S_KB1 = 8736, S_T3 = 0;
    int b = blockIdx.x;
    int tid = threadIdx.x;

    for (int i = tid; i < 735; i += 256) sm[S_IN + i] = xo[(long)b * 735 + i];
    if (tid < 256) sm[S_K1 + tid] = k1[tid];
    if (tid < 32)  sm[S_KB1 + tid] = kb1[tid];
    __syncthreads();

    // stage 1: conv(1->32,k8) + relu + pool3 -> t1[32][242]
    for (int o = tid; o < 32 * 242; o += 256) {
        int ch = o / 242;
        int p = o - ch * 242;
        int base = 3 * p;
        const float* w = &sm[S_K1 + ch * 8];
        float s0 = 0.f, s1 = 0.f, s2 = 0.f;
#pragma unroll
        for (int i = 0; i < 8; i++) {
            float wv = w[i];
            s0 = fmaf(sm[S_IN + base + i],     wv, s0);
            s1 = fmaf(sm[S_IN + base + 1 + i], wv, s1);
            s2 = fmaf(sm[S_IN + base + 2 + i], wv, s2);
        }
        float m = fmaxf(fmaxf(s0, s1), s2) + sm[S_KB1 + ch];
        sm[S_T1 + o] = fmaxf(m, 0.f);
    }
    __syncthreads();

    // stage 2: conv(32->64,k8)+relu+pool3 -> t2[64][78]
    {
        int oc0 = tid & 31;
        int oc1 = oc0 + 32;
        int tile = tid >> 5;
        float bb0 = kb2[oc0], bb1 = kb2[oc1];
        for (int p0 = tile * 3; p0 < 78; p0 += 24) {
            int q0 = 3 * p0;
            ull acc[9];
#pragma unroll
            for (int r = 0; r < 9; r++) acc[r] = 0ull;
            for (int ic = 0; ic < 32; ic++) {
                const float* wl = &k2t[ic * 8 * 64];
                ull w[8];
#pragma unroll
                for (int i = 0; i < 8; i++)
                    w[i] = pk2(wl[i * 64 + oc0], wl[i * 64 + oc1]);
                const float* t1r = &sm[S_T1 + ic * 242];
                ull ib[16];
#pragma unroll
                for (int i = 0; i < 16; i++) {
                    int q = q0 + i;
                    ib[i] = bc2(t1r[q < 242 ? q : 241]);
                }
#pragma unroll
                for (int i = 0; i < 8; i++)
#pragma unroll
                    for (int r = 0; r < 9; r++)
                        fma2(acc[r], ib[r + i], w[i]);
            }
#pragma unroll
            for (int pp = 0; pp < 3; pp++) {
                int p = p0 + pp;
                if (p < 78) {
                    float2 a0 = upk2(acc[3 * pp]);
                    float2 a1 = upk2(acc[3 * pp + 1]);
                    float2 a2 = upk2(acc[3 * pp + 2]);
                    float m0 = fmaxf(fmaxf(a0.x, a1.x), a2.x) + bb0;
                    float m1 = fmaxf(fmaxf(a0.y, a1.y), a2.y) + bb1;
                    sm[S_T2 + oc0 * 78 + p] = fmaxf(m0, 0.f);
                    sm[S_T2 + oc1 * 78 + p] = fmaxf(m1, 0.f);
                }
            }
        }
    }
    __syncthreads();

    // stage 3: conv(64->128,k8)+relu+pool3 -> t3[128][23]
    {
        int oc0 = tid & 63;
        int oc1 = oc0 + 64;
        int tile = tid >> 6;
        float bb0 = kb3[oc0], bb1 = kb3[oc1];
        for (int p0 = tile * 3; p0 < 23; p0 += 12) {
            int q0 = 3 * p0;
            ull acc[9];
#pragma unroll
            for (int r = 0; r < 9; r++) acc[r] = 0ull;
            for (int ic = 0; ic < 64; ic++) {
                const float* wl = &k3t[ic * 8 * 128];
                ull w[8];
#pragma unroll
                for (int i = 0; i < 8; i++)
                    w[i] = pk2(wl[i * 128 + oc0], wl[i * 128 + oc1]);
                const float* t2r = &sm[S_T2 + ic * 78];
                ull ib[16];
#pragma unroll
                for (int i = 0; i < 16; i++) {
                    int q = q0 + i;
                    ib[i] = bc2(t2r[q < 78 ? q : 77]);
                }
#pragma unroll
                for (int i = 0; i < 8; i++)
#pragma unroll
                    for (int r = 0; r < 9; r++)
                        fma2(acc[r], ib[r + i], w[i]);
            }
#pragma unroll
            for (int pp = 0; pp < 3; pp++) {
                int p = p0 + pp;
                if (p < 23) {
                    float2 a0 = upk2(acc[3 * pp]);
                    float2 a1 = upk2(acc[3 * pp + 1]);
                    float2 a2 = upk2(acc[3 * pp + 2]);
                    float m0 = fmaxf(fmaxf(a0.x, a1.x), a2.x) + bb0;
                    float m1 = fmaxf(fmaxf(a0.y, a1.y), a2.y) + bb1;
                    sm[S_T3 + oc0 * 23 + p] = fmaxf(m0, 0.f);
                    sm[S_T3 + oc1 * 23 + p] = fmaxf(m1, 0.f);
                }
            }
        }
    }
    __syncthreads();

    for (int i = tid; i < 2944; i += 256) tf[(long)b * 2944 + i] = sm[S_T3 + i];
}

// final dot: out[b] = c2[b,:] . Wo + bo
__global__ void k_out(const float* __restrict__ c2, const float* __restrict__ Wo,
                      const float* __restrict__ bo, float* __restrict__ out)
{
    int warp = (blockIdx.x * blockDim.x + threadIdx.x) >> 5;
    int lane = threadIdx.x & 31;
    if (warp >= NB) return;
    float s = 0.f;
#pragma unroll
    for (int i = lane; i < 128; i += 32) s = fmaf(c2[warp * 128 + i], Wo[i], s);
#pragma unroll
    for (int off = 16; off; off >>= 1) s += __shfl_down_sync(0xffffffffu, s, off);
    if (lane == 0) out[warp] = s + bo[0];
}

// ---------------- launch ----------------
static inline int cdiv(long a, long b) { return (int)((a + b - 1) / b); }

extern "C" void kernel_launch(void* const* d_in, const int* in_sizes, int n_in,
                              void* d_out, int out_size)
{
    const float* x    = (const float*)d_in[0];
    const int*   ei   = (const int*)d_in[1];
    const float* xo   = (const float*)d_in[3];
    const float* W1   = (const float*)d_in[4];  const float* b1  = (const float*)d_in[5];
    const float* W2   = (const float*)d_in[6];  const float* b2  = (const float*)d_in[7];
    const float* W3   = (const float*)d_in[8];  const float* b3  = (const float*)d_in[9];
    const float* Wg1  = (const float*)d_in[10]; const float* bg1 = (const float*)d_in[11];
    const float* Wg2  = (const float*)d_in[12]; const float* bg2 = (const float*)d_in[13];
    const float* k1   = (const float*)d_in[14]; const float* kb1 = (const float*)d_in[15];
    const float* k2   = (const float*)d_in[16]; const float* kb2 = (const float*)d_in[17];
    const float* k3   = (const float*)d_in[18]; const float* kb3 = (const float*)d_in[19];
    const float* Wxt  = (const float*)d_in[20]; const float* bxt = (const float*)d_in[21];
    const float* Wf1  = (const float*)d_in[22]; const float* bf1 = (const float*)d_in[23];
    const float* Wf2  = (const float*)d_in[24]; const float* bf2 = (const float*)d_in[25];
    const float* Wo   = (const float*)d_in[26]; const float* bo  = (const float*)d_in[27];
    const int* src = ei;
    const int* dst = ei + NE;
    float* out = (float*)d_out;

    float *p_u, *p_S, *p_h, *p_dinv, *p_g, *p_gh, *p_c, *p_c1, *p_c2, *p_tf, *p_k2t, *p_k3t;
    int *p_deg, *p_rowptr, *p_pos, *p_csr, *p_bsum;
    cudaGetSymbolAddress((void**)&p_u, g_u);
    cudaGetSymbolAddress((void**)&p_S, g_S);
    cudaGetSymbolAddress((void**)&p_h, g_h);
    cudaGetSymbolAddress((void**)&p_dinv, g_dinv);
    cudaGetSymbolAddress((void**)&p_deg, g_deg);
    cudaGetSymbolAddress((void**)&p_rowptr, g_rowptr);
    cudaGetSymbolAddress((void**)&p_pos, g_pos);
    cudaGetSymbolAddress((void**)&p_csr, g_csr);
    cudaGetSymbolAddress((void**)&p_bsum, g_bsum);
    cudaGetSymbolAddress((void**)&p_g, g_g);
    cudaGetSymbolAddress((void**)&p_gh, g_gh);
    cudaGetSymbolAddress((void**)&p_c, g_c);
    cudaGetSymbolAddress((void**)&p_c1, g_c1);
    cudaGetSymbolAddress((void**)&p_c2, g_c2);
    cudaGetSymbolAddress((void**)&p_tf, g_tf);
    cudaGetSymbolAddress((void**)&p_k2t, g_k2t);
    cudaGetSymbolAddress((void**)&p_k3t, g_k3t);

    cudaFuncSetAttribute(k_conv, cudaFuncAttributeMaxDynamicSharedMemorySize, 12736 * 4);

    // ---- side stream for the independent conv branch (created once; reused;
    //      identical work every call, so launches remain deterministic) ----
    static cudaStream_t s_conv = nullptr;
    static cudaEvent_t ev_fork = nullptr, ev_join = nullptr;
    if (s_conv == nullptr) {
        cudaStreamCreateWithFlags(&s_conv, cudaStreamNonBlocking);
        cudaEventCreateWithFlags(&ev_fork, cudaEventDisableTiming);
        cudaEventCreateWithFlags(&ev_join, cudaEventDisableTiming);
    }

    // fork: bring s_conv into the same dependency chain / capture graph
    cudaEventRecord(ev_fork, 0);
    cudaStreamWaitEvent(s_conv, ev_fork, 0);

    // ======== conv branch (stream s_conv) ========
    k_tr_k2<<<cdiv(64 * 32 * 8, 256), 256, 0, s_conv>>>(k2, p_k2t);
    k_tr_k3<<<cdiv(128 * 64 * 8, 256), 256, 0, s_conv>>>(k3, p_k3t);
    k_conv<<<NB, 256, 12736 * 4, s_conv>>>(xo, k1, kb1, p_k2t, kb2, p_k3t, kb3, p_tf);
    {
        dim3 grd(cdiv(128, 64), cdiv(NB, 128));
        k_gemm_tc<<<grd, 256, 0, s_conv>>>(p_tf, 2944, Wxt, bxt, nullptr,
                                           p_c + 128, 256, NB, 2944, 128, 128, 0);
    }
    cudaEventRecord(ev_join, s_conv);

    // ======== GCN branch (default stream) ========
    // degrees -> dinv ; CSR build
    k_zero_i<<<cdiv(NN, 256), 256>>>(p_deg, NN);
    k_degree<<<cdiv(NE, 256), 256>>>(dst, p_deg);
    k_dinv<<<cdiv(NN, 256), 256>>>(p_deg, p_dinv);
    k_scan_block<<<NBLK, 256>>>(p_deg, p_rowptr, p_bsum);
    k_scan_bsum<<<1, 256>>>(p_bsum);
    k_scan_add<<<cdiv(NN, 256), 256>>>(p_rowptr, p_bsum, p_pos);
    k_fill<<<cdiv(NE, 256), 256>>>(src, dst, p_pos, p_csr);

    // v1 = x * dinv (padded to 80 cols)
    k_scale_pad<<<cdiv((long)NN * 80, 256), 256>>>(x, p_dinv, p_u);

    // ---- GCN layer 1 ----
    k_gather<20><<<cdiv((long)NN * 20, 256), 256>>>(p_u, p_S, p_rowptr, p_csr, p_dinv);
    {
        dim3 grd(cdiv(80, 64), cdiv(NN, 128));
        k_gemm_tc<<<grd, 256>>>(p_S, 80, W1, b1, p_dinv,
                                p_h, 80, NN, 78, 78, 80, 1);
    }
    // ---- GCN layer 2 ----
    k_gather<20><<<cdiv((long)NN * 20, 256), 256>>>(p_h, p_S, p_rowptr, p_csr, p_dinv);
    {
        dim3 grd(cdiv(156, 64), cdiv(NN, 128));
        k_gemm_tc<<<grd, 256>>>(p_S, 80, W2, b2, p_dinv,
                                p_u, 156, NN, 78, 156, 156, 1);
    }
    // ---- GCN layer 3 ----
    k_gather<39><<<cdiv((long)NN * 39, 256), 256>>>(p_u, p_S, p_rowptr, p_csr, p_dinv);
    {
        dim3 grd(cdiv(312, 64), cdiv(NN, 128));
        k_gemm_tc<<<grd, 256>>>(p_S, 156, W3, b3, nullptr,
                                p_h, 312, NN, 156, 312, 312, 1);
    }

    // graph max pool + graph MLP -> c[:,0:128]
    k_segmax<<<NB, 128>>>(p_h, p_g);
    {
        dim3 grd(cdiv(1024, 64), cdiv(NB, 128));
        k_gemm_tc<<<grd, 256>>>(p_g, 312, Wg1, bg1, nullptr,
                                p_gh, 1024, NB, 312, 1024, 1024, 1);
    }
    {
        dim3 grd(cdiv(128, 64), cdiv(NB, 128));
        k_gemm_tc<<<grd, 256>>>(p_gh, 1024, Wg2, bg2, nullptr,
                                p_c, 256, NB, 1024, 128, 128, 0);
    }

    // join: conv branch must be done before the head reads c[:,128:256]
    cudaStreamWaitEvent(0, ev_join, 0);

    // head
    {
        dim3 grd(cdiv(1024, 64), cdiv(NB, 128));
        k_gemm_tc<<<grd, 256>>>(p_c, 256, Wf1, bf1, nullptr,
                                p_c1, 1024, NB, 256, 1024, 1024, 1);
    }
    {
        dim3 grd(cdiv(128, 64), cdiv(NB, 128));
        k_gemm_tc<<<grd, 256>>>(p_c1, 1024, Wf2, bf2, nullptr,
                                p_c2, 128, NB, 1024, 128, 128, 1);
    }
    k_out<<<cdiv(NB * 32, 256), 256>>>(p_c2, Wo, bo, out);
}